// round 6
// baseline (speedup 1.0000x reference)
#include <cuda_runtime.h>
#include <cstdint>

#define BB   4
#define NPQ  1024
#define NRK  1024
#define CDIM 1024
#define HH   16
#define DH   64

// Scratch (static device arrays: allocation-guard safe)
__device__ float g_q[(size_t)BB * NPQ * CDIM];
__device__ float g_k[(size_t)BB * NRK * CDIM];
__device__ float g_v[(size_t)BB * NRK * CDIM];
__device__ float g_rowsum[(size_t)BB * HH * NPQ];    // 256 KB

// ---------------------------------------------------------------------------
// helpers
// ---------------------------------------------------------------------------
__device__ __forceinline__ uint32_t f2tf32(float x) {
    uint32_t y;
    asm("cvt.rna.tf32.f32 %0, %1;" : "=r"(y) : "f"(x));
    return y;
}

__device__ __forceinline__ void mma_tf32(float c[4], const uint32_t a[4],
                                         const uint32_t b[2]) {
    asm volatile(
        "mma.sync.aligned.m16n8k8.row.col.f32.tf32.tf32.f32 "
        "{%0,%1,%2,%3}, {%4,%5,%6,%7}, {%8,%9}, {%0,%1,%2,%3};"
        : "+f"(c[0]), "+f"(c[1]), "+f"(c[2]), "+f"(c[3])
        : "r"(a[0]), "r"(a[1]), "r"(a[2]), "r"(a[3]), "r"(b[0]), "r"(b[1]));
}

__device__ __forceinline__ uint32_t smem_u32(const void* p) {
    uint32_t a;
    asm("{ .reg .u64 t; cvta.to.shared.u64 t, %1; cvt.u32.u64 %0, t; }"
        : "=r"(a) : "l"(p));
    return a;
}

#define CP_ASYNC16(dst, src) \
    asm volatile("cp.async.cg.shared.global [%0], [%1], 16;" \
                 :: "r"(dst), "l"(src) : "memory")
#define CP_COMMIT() asm volatile("cp.async.commit_group;" ::: "memory")
#define CP_WAIT1()  asm volatile("cp.async.wait_group 1;" ::: "memory")
#define CP_WAIT0()  asm volatile("cp.async.wait_group 0;" ::: "memory")

#define AS_STRIDE 36
#define AS_WORDS  (256 * AS_STRIDE)
#define BS_STRIDE 36

// ---------------------------------------------------------------------------
// TF32 NT GEMM. Block 256x128, 8 warps (4m x 2n), warp 64x64, cp.async.
// MODE 0: C = A*B^T + bias.   MODE 2: rowsum[m] += sum_n exp(alpha*S) only.
// ---------------------------------------------------------------------------
template <int MODE>
__global__ void __launch_bounds__(256, 1) gemm_nt(
    const float* __restrict__ Ag, const float* __restrict__ Bg,
    const float* __restrict__ bias, float* __restrict__ Cg,
    float* __restrict__ rowsum,
    int KT, int lda, int ldb, int ldc,
    long long sAo, long long sAi, long long sBo, long long sBi,
    float alpha)
{
    extern __shared__ float sm[];
    float* As = sm;                  // [256][36]
    float* Bs = sm + AS_WORDS;       // [128][36]

    const int tid = threadIdx.x;
    const int z = blockIdx.z;
    const long long zb = z >> 4, zh = z & 15;
    const float* A = Ag + zb * sAo + zh * sAi;
    const float* B = Bg + zb * sBo + zh * sBi;
    const int m0 = blockIdx.y << 8, n0 = blockIdx.x << 7;

    const int warp = tid >> 5, lane = tid & 31;
    const int g = lane >> 2, t = lane & 3;
    const int wm = (warp >> 1) << 6;
    const int wn = (warp & 1) << 6;

    const uint32_t sA = smem_u32(As);
    const uint32_t sB = smem_u32(Bs);

    const int lrow = tid >> 2;
    const int lc   = (tid & 3) << 2;

    auto load_stage = [&](int kt) {
        const int so = (kt & 1) << 4;
        const int k0 = kt << 4;
#pragma unroll
        for (int i = 0; i < 4; i++) {
            int r = lrow + (i << 6);
            CP_ASYNC16(sA + ((r * AS_STRIDE + so + lc) << 2),
                       A + (size_t)(m0 + r) * lda + k0 + lc);
        }
#pragma unroll
        for (int i = 0; i < 2; i++) {
            int r = lrow + (i << 6);
            CP_ASYNC16(sB + ((r * BS_STRIDE + so + lc) << 2),
                       B + (size_t)(n0 + r) * ldb + k0 + lc);
        }
        CP_COMMIT();
    };

    float acc[4][8][4];
#pragma unroll
    for (int i = 0; i < 4; i++)
#pragma unroll
        for (int j = 0; j < 8; j++)
#pragma unroll
            for (int l = 0; l < 4; l++) acc[i][j][l] = 0.f;

    load_stage(0);

    for (int kt = 0; kt < KT; kt++) {
        const bool pf = (kt + 1 < KT);
        if (pf) { load_stage(kt + 1); CP_WAIT1(); } else { CP_WAIT0(); }
        __syncthreads();

        const int so = (kt & 1) << 4;
#pragma unroll
        for (int kk = 0; kk < 16; kk += 8) {
            uint32_t a[4][4], b[8][2];
#pragma unroll
            for (int mt = 0; mt < 4; mt++) {
                const float* pr = As + (wm + (mt << 4) + g) * AS_STRIDE + so + kk;
                a[mt][0] = f2tf32(pr[t]);
                a[mt][1] = f2tf32(pr[8 * AS_STRIDE + t]);
                a[mt][2] = f2tf32(pr[t + 4]);
                a[mt][3] = f2tf32(pr[8 * AS_STRIDE + t + 4]);
            }
#pragma unroll
            for (int nt = 0; nt < 8; nt++) {
                const float* pr = Bs + (wn + (nt << 3) + g) * BS_STRIDE + so + kk;
                b[nt][0] = f2tf32(pr[t]);
                b[nt][1] = f2tf32(pr[t + 4]);
            }
#pragma unroll
            for (int mt = 0; mt < 4; mt++)
#pragma unroll
                for (int nt = 0; nt < 8; nt++)
                    mma_tf32(acc[mt][nt], a[mt], b[nt]);
        }
        __syncthreads();
    }

    if (MODE == 0) {
#pragma unroll
        for (int mt = 0; mt < 4; mt++) {
            int m = m0 + wm + (mt << 4) + g;
#pragma unroll
            for (int nt = 0; nt < 8; nt++) {
                int n = n0 + wn + (nt << 3) + 2 * t;
                float b0v = bias[n], b1v = bias[n + 1];
                float2 o0, o1;
                o0.x = acc[mt][nt][0] + b0v;
                o0.y = acc[mt][nt][1] + b1v;
                o1.x = acc[mt][nt][2] + b0v;
                o1.y = acc[mt][nt][3] + b1v;
                *reinterpret_cast<float2*>(Cg + (size_t)z * 0 + (size_t)m * ldc + n) = o0;
                *reinterpret_cast<float2*>(Cg + (size_t)(m + 8) * ldc + n) = o1;
            }
        }
    } else {
#pragma unroll
        for (int mt = 0; mt < 4; mt++) {
            int m = m0 + wm + (mt << 4) + g;
            float r0 = 0.f, r1 = 0.f;
#pragma unroll
            for (int nt = 0; nt < 8; nt++) {
                r0 += __expf(acc[mt][nt][0] * alpha) + __expf(acc[mt][nt][1] * alpha);
                r1 += __expf(acc[mt][nt][2] * alpha) + __expf(acc[mt][nt][3] * alpha);
            }
            r0 += __shfl_xor_sync(0xffffffffu, r0, 1);
            r0 += __shfl_xor_sync(0xffffffffu, r0, 2);
            r1 += __shfl_xor_sync(0xffffffffu, r1, 1);
            r1 += __shfl_xor_sync(0xffffffffu, r1, 2);
            if (t == 0) {
                float* rs = rowsum + (size_t)z * NPQ;
                atomicAdd(&rs[m], r0);
                atomicAdd(&rs[m + 8], r1);
            }
        }
    }
}

// ---------------------------------------------------------------------------
// Fused pass B: block = (rc, qt, bp). For the 16 z = b*16 + bp*4 + j it
// recomputes S = q.k^T (128x128, K=64), Pn = exp(S/32)*inv, accumulates
// Aavg in registers (stored once, no atomics), and atomically adds Pn@V
// into O.
// ---------------------------------------------------------------------------
#define QS_STRIDE 68
#define PS_STRIDE 132
// dynamic smem words: q 128*68, k 128*68, v 128*68, P 128*132, sinv 128
#define FB_QOFF 0
#define FB_KOFF (128 * QS_STRIDE)
#define FB_VOFF (2 * 128 * QS_STRIDE)
#define FB_POFF (3 * 128 * QS_STRIDE)
#define FB_IOFF (3 * 128 * QS_STRIDE + 128 * PS_STRIDE)
#define FB_WORDS (FB_IOFF + 128)

__global__ void __launch_bounds__(256, 1) fused_ov(
    const float* __restrict__ qg, const float* __restrict__ kg,
    const float* __restrict__ vg, const float* __restrict__ rowsum,
    float* __restrict__ O, float* __restrict__ Aavg)
{
    extern __shared__ float sm[];
    float* qs = sm + FB_QOFF;
    float* ks = sm + FB_KOFF;
    float* vs = sm + FB_VOFF;
    float* ps = sm + FB_POFF;
    float* sinv = sm + FB_IOFF;

    const int rc = blockIdx.x, qt = blockIdx.y, bp = blockIdx.z;
    const int qbase = qt << 7, rbase = rc << 7;

    const int tid = threadIdx.x;
    const int warp = tid >> 5, lane = tid & 31;
    const int g = lane >> 2, t = lane & 3;
    const int wm = (warp >> 1) << 5;   // S/P rows: 0,32,64,96
    const int wn = (warp & 1) << 6;    // S cols: 0,64
    const int wn2 = (warp & 1) << 5;   // O cols: 0,32

    const uint32_t sq = smem_u32(qs);
    const uint32_t sk = smem_u32(ks);
    const uint32_t sv = smem_u32(vs);

    const int lrow = tid >> 1;           // 0..127
    const int lh = (tid & 1) << 5;       // 0 or 32 floats

    float aacc[2][8][4];
#pragma unroll
    for (int i = 0; i < 2; i++)
#pragma unroll
        for (int j = 0; j < 8; j++)
#pragma unroll
            for (int l = 0; l < 4; l++) aacc[i][j][l] = 0.f;

    for (int zi = 0; zi < 16; zi++) {
        const int b = zi >> 2;
        const int head = (bp << 2) + (zi & 3);
        const int z = b * HH + head;

        // load q, k, v tiles
        {
            const float* pq = qg + ((size_t)(b * NPQ + qbase + lrow)) * CDIM +
                              head * DH + lh;
            const float* pk = kg + ((size_t)(b * NRK + rbase + lrow)) * CDIM +
                              head * DH + lh;
            const float* pv = vg + ((size_t)(b * NRK + rbase + lrow)) * CDIM +
                              head * DH + lh;
            const uint32_t dq = sq + ((lrow * QS_STRIDE + lh) << 2);
            const uint32_t dk = sk + ((lrow * QS_STRIDE + lh) << 2);
            const uint32_t dv = sv + ((lrow * QS_STRIDE + lh) << 2);
#pragma unroll
            for (int i = 0; i < 8; i++) {
                CP_ASYNC16(dq + (i << 4), pq + (i << 2));
                CP_ASYNC16(dk + (i << 4), pk + (i << 2));
                CP_ASYNC16(dv + (i << 4), pv + (i << 2));
            }
            CP_COMMIT();
        }
        if (tid < 128)
            sinv[tid] = 1.0f / rowsum[(size_t)z * NPQ + qbase + tid];
        CP_WAIT0();
        __syncthreads();

        // S = q.k^T  (128x128, K=64)
        float sacc[2][8][4];
#pragma unroll
        for (int i = 0; i < 2; i++)
#pragma unroll
            for (int j = 0; j < 8; j++)
#pragma unroll
                for (int l = 0; l < 4; l++) sacc[i][j][l] = 0.f;

#pragma unroll
        for (int kk = 0; kk < 64; kk += 8) {
            uint32_t a[2][4], bfr[8][2];
#pragma unroll
            for (int mt = 0; mt < 2; mt++) {
                const float* pr = qs + (wm + (mt << 4) + g) * QS_STRIDE + kk;
                a[mt][0] = f2tf32(pr[t]);
                a[mt][1] = f2tf32(pr[8 * QS_STRIDE + t]);
                a[mt][2] = f2tf32(pr[t + 4]);
                a[mt][3] = f2tf32(pr[8 * QS_STRIDE + t + 4]);
            }
#pragma unroll
            for (int nt = 0; nt < 8; nt++) {
                const float* pr = ks + (wn + (nt << 3) + g) * QS_STRIDE + kk;
                bfr[nt][0] = f2tf32(pr[t]);
                bfr[nt][1] = f2tf32(pr[t + 4]);
            }
#pragma unroll
            for (int mt = 0; mt < 2; mt++)
#pragma unroll
                for (int nt = 0; nt < 8; nt++)
                    mma_tf32(sacc[mt][nt], a[mt], bfr[nt]);
        }

        // Pn = exp(S/32)*inv ; accumulate Aavg ; write Pn to smem
#pragma unroll
        for (int mt = 0; mt < 2; mt++) {
            const int r0 = wm + (mt << 4) + g;
            const float i0 = sinv[r0], i1 = sinv[r0 + 8];
#pragma unroll
            for (int nt = 0; nt < 8; nt++) {
                float p0 = __expf(sacc[mt][nt][0] * 0.03125f) * i0;
                float p1 = __expf(sacc[mt][nt][1] * 0.03125f) * i0;
                float p2 = __expf(sacc[mt][nt][2] * 0.03125f) * i1;
                float p3 = __expf(sacc[mt][nt][3] * 0.03125f) * i1;
                aacc[mt][nt][0] += p0; aacc[mt][nt][1] += p1;
                aacc[mt][nt][2] += p2; aacc[mt][nt][3] += p3;
                const int n = wn + (nt << 3) + 2 * t;
                *reinterpret_cast<float2*>(ps + (size_t)r0 * PS_STRIDE + n) =
                    make_float2(p0, p1);
                *reinterpret_cast<float2*>(ps + (size_t)(r0 + 8) * PS_STRIDE + n) =
                    make_float2(p2, p3);
            }
        }
        __syncthreads();

        // O_z = Pn @ V  (128x64, K=128), atomic accumulate
        float oacc[2][4][4];
#pragma unroll
        for (int i = 0; i < 2; i++)
#pragma unroll
            for (int j = 0; j < 4; j++)
#pragma unroll
                for (int l = 0; l < 4; l++) oacc[i][j][l] = 0.f;

#pragma unroll
        for (int kk = 0; kk < 128; kk += 8) {
            uint32_t a[2][4], bfr[4][2];
#pragma unroll
            for (int mt = 0; mt < 2; mt++) {
                const float* pr = ps + (wm + (mt << 4) + g) * PS_STRIDE + kk;
                a[mt][0] = f2tf32(pr[t]);
                a[mt][1] = f2tf32(pr[8 * PS_STRIDE + t]);
                a[mt][2] = f2tf32(pr[t + 4]);
                a[mt][3] = f2tf32(pr[8 * PS_STRIDE + t + 4]);
            }
#pragma unroll
            for (int nt = 0; nt < 4; nt++) {
                const float* pr = vs + (size_t)(kk + t) * QS_STRIDE +
                                  wn2 + (nt << 3) + g;
                bfr[nt][0] = f2tf32(pr[0]);
                bfr[nt][1] = f2tf32(pr[4 * QS_STRIDE]);
            }
#pragma unroll
            for (int mt = 0; mt < 2; mt++)
#pragma unroll
                for (int nt = 0; nt < 4; nt++)
                    mma_tf32(oacc[mt][nt], a[mt], bfr[nt]);
        }

        float* Ob = O + ((size_t)b * NPQ) * CDIM + head * DH;
#pragma unroll
        for (int mt = 0; mt < 2; mt++) {
            const int m = qbase + wm + (mt << 4) + g;
#pragma unroll
            for (int nt = 0; nt < 4; nt++) {
                const int n = wn2 + (nt << 3) + 2 * t;
                atomicAdd(Ob + (size_t)m * CDIM + n,     oacc[mt][nt][0]);
                atomicAdd(Ob + (size_t)m * CDIM + n + 1, oacc[mt][nt][1]);
                atomicAdd(Ob + (size_t)(m + 8) * CDIM + n,     oacc[mt][nt][2]);
                atomicAdd(Ob + (size_t)(m + 8) * CDIM + n + 1, oacc[mt][nt][3]);
            }
        }
        __syncthreads();
    }

    // store Aavg (disjoint per block, plain stores)
    float* Ab = Aavg + ((size_t)bp * NPQ) * NRK;
    const float sc = 1.0f / 16.0f;
#pragma unroll
    for (int mt = 0; mt < 2; mt++) {
        const int m = qbase + wm + (mt << 4) + g;
#pragma unroll
        for (int nt = 0; nt < 8; nt++) {
            const int n = rbase + wn + (nt << 3) + 2 * t;
            *reinterpret_cast<float2*>(Ab + (size_t)m * NRK + n) =
                make_float2(aacc[mt][nt][0] * sc, aacc[mt][nt][1] * sc);
            *reinterpret_cast<float2*>(Ab + (size_t)(m + 8) * NRK + n) =
                make_float2(aacc[mt][nt][2] * sc, aacc[mt][nt][3] * sc);
        }
    }
}

// ---------------------------------------------------------------------------
#define NT_SMEM ((AS_WORDS + 128 * BS_STRIDE) * 4)
#define FB_SMEM (FB_WORDS * 4)

extern "C" void kernel_launch(void* const* d_in, const int* in_sizes, int n_in,
                              void* d_out, int out_size)
{
    const float* Q  = (const float*)d_in[0];
    const float* K  = (const float*)d_in[1];
    const float* Wq = (const float*)d_in[2];
    const float* bq = (const float*)d_in[3];
    const float* Wk = (const float*)d_in[4];
    const float* bk = (const float*)d_in[5];
    const float* Wv = (const float*)d_in[6];
    const float* bv = (const float*)d_in[7];

    float* O    = (float*)d_out;
    float* Aavg = O + (size_t)BB * NPQ * CDIM;

    static float *pq = nullptr, *pk = nullptr, *pv = nullptr, *pR = nullptr;
    if (!pq) {
        cudaGetSymbolAddress((void**)&pq, g_q);
        cudaGetSymbolAddress((void**)&pk, g_k);
        cudaGetSymbolAddress((void**)&pv, g_v);
        cudaGetSymbolAddress((void**)&pR, g_rowsum);
        cudaFuncSetAttribute(gemm_nt<0>,
                             cudaFuncAttributeMaxDynamicSharedMemorySize, NT_SMEM);
        cudaFuncSetAttribute(gemm_nt<2>,
                             cudaFuncAttributeMaxDynamicSharedMemorySize, NT_SMEM);
        cudaFuncSetAttribute(fused_ov,
                             cudaFuncAttributeMaxDynamicSharedMemorySize, FB_SMEM);
    }

    // zero rowsum and O (atomic targets)
    cudaMemsetAsync(pR, 0, (size_t)BB * HH * NPQ * sizeof(float));
    cudaMemsetAsync(O, 0, (size_t)BB * NPQ * CDIM * sizeof(float));

    // 1) projections (M=4096, N=K=1024)
    dim3 gp(CDIM / 128, (BB * NPQ) / 256, 1);
    gemm_nt<0><<<gp, 256, NT_SMEM>>>(Q, Wq, bq, pq, nullptr,
                                     CDIM / 16, CDIM, CDIM, CDIM,
                                     0, 0, 0, 0, 1.0f);
    gemm_nt<0><<<gp, 256, NT_SMEM>>>(K, Wk, bk, pk, nullptr,
                                     CDIM / 16, CDIM, CDIM, CDIM,
                                     0, 0, 0, 0, 1.0f);
    gemm_nt<0><<<gp, 256, NT_SMEM>>>(K, Wv, bv, pv, nullptr,
                                     CDIM / 16, CDIM, CDIM, CDIM,
                                     0, 0, 0, 0, 1.0f);

    // 2) pass A: rowsum[z,q] = sum_r exp(q.k/32)
    dim3 gs(NRK / 128, NPQ / 256, BB * HH);
    gemm_nt<2><<<gs, 256, NT_SMEM>>>(pq, pk, nullptr, nullptr, pR,
                                     DH / 16, CDIM, CDIM, 0,
                                     (long long)NPQ * CDIM, DH,
                                     (long long)NRK * CDIM, DH,
                                     0.03125f);

    // 3) pass B: fused O (+atomics) and Aavg
    dim3 gf(NRK / 128, NPQ / 128, BB);
    fused_ov<<<gf, 256, FB_SMEM>>>(pq, pk, pv, pR, O, Aavg);
}

// round 7
// speedup vs baseline: 1.1655x; 1.1655x over previous
#include <cuda_runtime.h>
#include <cstdint>

#define BB   4
#define NPQ  1024
#define NRK  1024
#define CDIM 1024
#define HH   16
#define DH   64

// Scratch (static device arrays: allocation-guard safe)
__device__ float g_q[(size_t)BB * NPQ * CDIM];
__device__ float g_k[(size_t)BB * NRK * CDIM];
__device__ float g_v[(size_t)BB * NRK * CDIM];
__device__ float g_P[(size_t)BB * HH * NPQ * NRK];   // 256 MB (tf32-rounded)
__device__ float g_rowsum[(size_t)BB * HH * NPQ];    // 256 KB

// ---------------------------------------------------------------------------
// helpers
// ---------------------------------------------------------------------------
__device__ __forceinline__ uint32_t f2tf32(float x) {
    uint32_t y;
    asm("cvt.rna.tf32.f32 %0, %1;" : "=r"(y) : "f"(x));
    return y;
}
__device__ __forceinline__ float rnd_tf32(float x) {
    return __uint_as_float(f2tf32(x));
}

__device__ __forceinline__ void mma_tf32(float c[4], const uint32_t a[4],
                                         const uint32_t b[2]) {
    asm volatile(
        "mma.sync.aligned.m16n8k8.row.col.f32.tf32.tf32.f32 "
        "{%0,%1,%2,%3}, {%4,%5,%6,%7}, {%8,%9}, {%0,%1,%2,%3};"
        : "+f"(c[0]), "+f"(c[1]), "+f"(c[2]), "+f"(c[3])
        : "r"(a[0]), "r"(a[1]), "r"(a[2]), "r"(a[3]), "r"(b[0]), "r"(b[1]));
}

__device__ __forceinline__ uint32_t smem_u32(const void* p) {
    uint32_t a;
    asm("{ .reg .u64 t; cvta.to.shared.u64 t, %1; cvt.u32.u64 %0, t; }"
        : "=r"(a) : "l"(p));
    return a;
}

#define CP_ASYNC16(dst, src) \
    asm volatile("cp.async.cg.shared.global [%0], [%1], 16;" \
                 :: "r"(dst), "l"(src) : "memory")
#define CP_COMMIT() asm volatile("cp.async.commit_group;" ::: "memory")
#define CP_WAIT1()  asm volatile("cp.async.wait_group 1;" ::: "memory")
#define CP_WAIT0()  asm volatile("cp.async.wait_group 0;" ::: "memory")

// 3-stage ring strides (48 k-cols + 4 pad): 52g mod 32 = 20g, distinct g<8.
#define R3_STRIDE 52
// scores single-shot stride (64 + 4 pad): 68g mod 32 = 4g, distinct g<8.
#define SC_STRIDE 68
// out-gemm V stride
#define VS_STRIDE 72

// ---------------------------------------------------------------------------
// Projection GEMM (NT): C = round_tf32(A*B^T + bias).
// Tile 128x128, 256 thr, 8 warps (4m x 2n), warp 32x64, 3-stage cp.async.
// Fragments cvt'd in-loop (raw inputs).
// ---------------------------------------------------------------------------
__global__ void __launch_bounds__(256, 2) proj_gemm(
    const float* __restrict__ Ag, const float* __restrict__ Bg,
    const float* __restrict__ bias, float* __restrict__ Cg)
{
    extern __shared__ float sm[];
    float* As = sm;                      // [128][52]
    float* Bs = sm + 128 * R3_STRIDE;    // [128][52]

    const int tid = threadIdx.x;
    const int m0 = blockIdx.y << 7, n0 = blockIdx.x << 7;
    const int warp = tid >> 5, lane = tid & 31;
    const int g = lane >> 2, t = lane & 3;
    const int wm = (warp >> 1) << 5;   // 0,32,64,96
    const int wn = (warp & 1) << 6;    // 0,64

    const uint32_t sA = smem_u32(As);
    const uint32_t sB = smem_u32(Bs);
    const int lrow = tid >> 1;           // 0..127
    const int lc0 = ((tid & 1) << 1);    // chunk 0/2

    auto load_stage = [&](int kt) {
        const int so = (kt % 3) << 4;
        const int k0 = kt << 4;
#pragma unroll
        for (int i = 0; i < 2; i++) {
            int col = (lc0 + i) << 2;
            CP_ASYNC16(sA + ((lrow * R3_STRIDE + so + col) << 2),
                       Ag + (size_t)(m0 + lrow) * CDIM + k0 + col);
            CP_ASYNC16(sB + ((lrow * R3_STRIDE + so + col) << 2),
                       Bg + (size_t)(n0 + lrow) * CDIM + k0 + col);
        }
        CP_COMMIT();
    };

    float acc[2][8][4];
#pragma unroll
    for (int i = 0; i < 2; i++)
#pragma unroll
        for (int j = 0; j < 8; j++)
#pragma unroll
            for (int l = 0; l < 4; l++) acc[i][j][l] = 0.f;

    const int KT = CDIM / 16;
    load_stage(0);
    load_stage(1);

    for (int kt = 0; kt < KT; kt++) {
        if (kt + 1 < KT) { CP_WAIT1(); } else { CP_WAIT0(); }
        __syncthreads();
        if (kt + 2 < KT) load_stage(kt + 2);

        const int so = (kt % 3) << 4;
#pragma unroll
        for (int kk = 0; kk < 16; kk += 8) {
            uint32_t a[2][4], b[8][2];
#pragma unroll
            for (int mt = 0; mt < 2; mt++) {
                const float* pr = As + (wm + (mt << 4) + g) * R3_STRIDE + so + kk;
                a[mt][0] = f2tf32(pr[t]);
                a[mt][1] = f2tf32(pr[8 * R3_STRIDE + t]);
                a[mt][2] = f2tf32(pr[t + 4]);
                a[mt][3] = f2tf32(pr[8 * R3_STRIDE + t + 4]);
            }
#pragma unroll
            for (int nt = 0; nt < 8; nt++) {
                const float* pr = Bs + (wn + (nt << 3) + g) * R3_STRIDE + so + kk;
                b[nt][0] = f2tf32(pr[t]);
                b[nt][1] = f2tf32(pr[t + 4]);
            }
#pragma unroll
            for (int mt = 0; mt < 2; mt++)
#pragma unroll
                for (int nt = 0; nt < 8; nt++)
                    mma_tf32(acc[mt][nt], a[mt], b[nt]);
        }
        __syncthreads();
    }

#pragma unroll
    for (int mt = 0; mt < 2; mt++) {
        int m = m0 + wm + (mt << 4) + g;
#pragma unroll
        for (int nt = 0; nt < 8; nt++) {
            int n = n0 + wn + (nt << 3) + 2 * t;
            float b0v = bias[n], b1v = bias[n + 1];
            float2 o0, o1;
            o0.x = rnd_tf32(acc[mt][nt][0] + b0v);
            o0.y = rnd_tf32(acc[mt][nt][1] + b1v);
            o1.x = rnd_tf32(acc[mt][nt][2] + b0v);
            o1.y = rnd_tf32(acc[mt][nt][3] + b1v);
            *reinterpret_cast<float2*>(Cg + (size_t)m * CDIM + n) = o0;
            *reinterpret_cast<float2*>(Cg + (size_t)(m + 8) * CDIM + n) = o1;
        }
    }
}

// ---------------------------------------------------------------------------
// Scores: P = round_tf32(exp(q.k^T/32)), rowsum += sums. Inputs pre-rounded
// (no cvt). Tile 128x128, K=64 single-shot smem, one sync, 128 mma/warp.
// ---------------------------------------------------------------------------
__global__ void __launch_bounds__(256, 2) scores_gemm(
    const float* __restrict__ qg, const float* __restrict__ kg,
    float* __restrict__ P, float* __restrict__ rowsum)
{
    extern __shared__ float sm[];
    float* qs = sm;                      // [128][68]
    float* ks = sm + 128 * SC_STRIDE;    // [128][68]

    const int tid = threadIdx.x;
    const int z = blockIdx.z;
    const long long zb = z >> 4, zh = z & 15;
    const float* A = qg + zb * ((long long)NPQ * CDIM) + zh * DH;
    const float* B = kg + zb * ((long long)NRK * CDIM) + zh * DH;
    float* C = P + (long long)z * NPQ * NRK;
    const int m0 = blockIdx.y << 7, n0 = blockIdx.x << 7;

    const int warp = tid >> 5, lane = tid & 31;
    const int g = lane >> 2, t = lane & 3;
    const int wm = (warp >> 1) << 5;
    const int wn = (warp & 1) << 6;

    const uint32_t sq = smem_u32(qs);
    const uint32_t sk = smem_u32(ks);
    const int lrow = tid >> 1;           // 0..127
    const int lh = (tid & 1) << 5;       // 0 / 32 floats

    {
        const float* pa = A + (size_t)(m0 + lrow) * CDIM + lh;
        const float* pb = B + (size_t)(n0 + lrow) * CDIM + lh;
        const uint32_t dq = sq + ((lrow * SC_STRIDE + lh) << 2);
        const uint32_t dk = sk + ((lrow * SC_STRIDE + lh) << 2);
#pragma unroll
        for (int i = 0; i < 8; i++) {
            CP_ASYNC16(dq + (i << 4), pa + (i << 2));
            CP_ASYNC16(dk + (i << 4), pb + (i << 2));
        }
        CP_COMMIT();
    }
    CP_WAIT0();
    __syncthreads();

    float acc[2][8][4];
#pragma unroll
    for (int i = 0; i < 2; i++)
#pragma unroll
        for (int j = 0; j < 8; j++)
#pragma unroll
            for (int l = 0; l < 4; l++) acc[i][j][l] = 0.f;

    const uint32_t* qu = reinterpret_cast<const uint32_t*>(qs);
    const uint32_t* ku = reinterpret_cast<const uint32_t*>(ks);
#pragma unroll
    for (int kk = 0; kk < 64; kk += 8) {
        uint32_t a[2][4], b[8][2];
#pragma unroll
        for (int mt = 0; mt < 2; mt++) {
            const uint32_t* pr = qu + (wm + (mt << 4) + g) * SC_STRIDE + kk;
            a[mt][0] = pr[t];
            a[mt][1] = pr[8 * SC_STRIDE + t];
            a[mt][2] = pr[t + 4];
            a[mt][3] = pr[8 * SC_STRIDE + t + 4];
        }
#pragma unroll
        for (int nt = 0; nt < 8; nt++) {
            const uint32_t* pr = ku + (wn + (nt << 3) + g) * SC_STRIDE + kk;
            b[nt][0] = pr[t];
            b[nt][1] = pr[t + 4];
        }
#pragma unroll
        for (int mt = 0; mt < 2; mt++)
#pragma unroll
            for (int nt = 0; nt < 8; nt++)
                mma_tf32(acc[mt][nt], a[mt], b[nt]);
    }

    const float alpha = 0.03125f;
#pragma unroll
    for (int mt = 0; mt < 2; mt++) {
        int m = m0 + wm + (mt << 4) + g;
        float r0 = 0.f, r1 = 0.f;
#pragma unroll
        for (int nt = 0; nt < 8; nt++) {
            int n = n0 + wn + (nt << 3) + 2 * t;
            float e0 = rnd_tf32(__expf(acc[mt][nt][0] * alpha));
            float e1 = rnd_tf32(__expf(acc[mt][nt][1] * alpha));
            float e2 = rnd_tf32(__expf(acc[mt][nt][2] * alpha));
            float e3 = rnd_tf32(__expf(acc[mt][nt][3] * alpha));
            r0 += e0 + e1;
            r1 += e2 + e3;
            *reinterpret_cast<float2*>(C + (size_t)m * NRK + n) =
                make_float2(e0, e1);
            *reinterpret_cast<float2*>(C + (size_t)(m + 8) * NRK + n) =
                make_float2(e2, e3);
        }
        r0 += __shfl_xor_sync(0xffffffffu, r0, 1);
        r0 += __shfl_xor_sync(0xffffffffu, r0, 2);
        r1 += __shfl_xor_sync(0xffffffffu, r1, 1);
        r1 += __shfl_xor_sync(0xffffffffu, r1, 2);
        if (t == 0) {
            float* rs = rowsum + (size_t)z * NPQ;
            atomicAdd(&rs[m], r0);
            atomicAdd(&rs[m + 8], r1);
        }
    }
}

// ---------------------------------------------------------------------------
// A_avg[b',q,r] = (1/16) sum_{b,j} P[b,4b'+j,q,r] * inv[b,4b'+j,q]
// ---------------------------------------------------------------------------
__global__ void __launch_bounds__(256) avg_kernel(
    const float* __restrict__ P, const float* __restrict__ rowsum,
    float* __restrict__ Aavg)
{
    __shared__ float sinv[16];
    const int q = blockIdx.x & 1023;
    const int bp = blockIdx.x >> 10;
    const int t = threadIdx.x;

    if (t < 16) {
        int b = t >> 2, j = t & 3;
        sinv[t] = 1.0f / rowsum[((size_t)(b * HH + bp * 4 + j)) * NPQ + q];
    }
    __syncthreads();

    float ax = 0.f, ay = 0.f, az = 0.f, aw = 0.f;
#pragma unroll
    for (int b = 0; b < 4; b++)
#pragma unroll
        for (int j = 0; j < 4; j++) {
            const float* p = P + ((((size_t)(b * HH + bp * 4 + j)) << 10 | q) << 10);
            float4 v = *reinterpret_cast<const float4*>(p + t * 4);
            float f = sinv[b * 4 + j];
            ax = fmaf(v.x, f, ax); ay = fmaf(v.y, f, ay);
            az = fmaf(v.z, f, az); aw = fmaf(v.w, f, aw);
        }
    const float sc = 1.0f / 16.0f;
    float4 o = make_float4(ax * sc, ay * sc, az * sc, aw * sc);
    *reinterpret_cast<float4*>(Aavg + (((size_t)blockIdx.x) << 10) + t * 4) = o;
}

// ---------------------------------------------------------------------------
// Out GEMM (NN) per (b,h): O[q, h*64+d] = inv[q]*sum_r P[q,r]*V[r, h*64+d]
// Tile 256x64, 8 warps (4m x 2n), warp 64x32, 3-stage cp.async, no cvt
// (P and V pre-rounded).
// ---------------------------------------------------------------------------
__global__ void __launch_bounds__(256, 2) out_gemm(
    const float* __restrict__ Pg, const float* __restrict__ Vg,
    const float* __restrict__ rowsum, float* __restrict__ Og)
{
    extern __shared__ float sm[];
    float* As = sm;                      // [256][52]
    float* Vs = sm + 256 * R3_STRIDE;    // [48][72]

    const int tid = threadIdx.x;
    const int z = blockIdx.y;
    const long long zb = z >> 4, zh = z & 15;
    const float* A = Pg + ((long long)z * NPQ) * NRK;
    const float* B = Vg + zb * ((long long)NRK * CDIM) + zh * DH;
    float* C = Og + zb * ((long long)NPQ * CDIM) + zh * DH;

    const int m0 = blockIdx.x << 8;
    const int warp = tid >> 5, lane = tid & 31;
    const int g = lane >> 2, t = lane & 3;
    const int wm = (warp >> 1) << 6;   // 0..192
    const int wn = (warp & 1) << 5;    // 0,32

    const uint32_t sA = smem_u32(As);
    const uint32_t sV = smem_u32(Vs);

    const int lrow = tid >> 2;          // 0..63 (A rows, 4 per thread)
    const int lc   = (tid & 3) << 2;
    const int vk = tid >> 4;            // 0..15
    const int vc = (tid & 15) << 2;     // 0..60

    auto load_stage = [&](int kt) {
        const int so = (kt % 3) << 4;
        const int k0 = kt << 4;
#pragma unroll
        for (int i = 0; i < 4; i++) {
            int r = lrow + (i << 6);
            CP_ASYNC16(sA + ((r * R3_STRIDE + so + lc) << 2),
                       A + (size_t)(m0 + r) * NRK + k0 + lc);
        }
        CP_ASYNC16(sV + (((so + vk) * VS_STRIDE + vc) << 2),
                   B + (size_t)(k0 + vk) * CDIM + vc);
        CP_COMMIT();
    };

    float acc[4][4][4];
#pragma unroll
    for (int i = 0; i < 4; i++)
#pragma unroll
        for (int j = 0; j < 4; j++)
#pragma unroll
            for (int l = 0; l < 4; l++) acc[i][j][l] = 0.f;

    const int KT = NRK / 16;
    load_stage(0);
    load_stage(1);

    const uint32_t* au = reinterpret_cast<const uint32_t*>(As);
    const uint32_t* vu = reinterpret_cast<const uint32_t*>(Vs);

    for (int kt = 0; kt < KT; kt++) {
        if (kt + 1 < KT) { CP_WAIT1(); } else { CP_WAIT0(); }
        __syncthreads();
        if (kt + 2 < KT) load_stage(kt + 2);

        const int so = (kt % 3) << 4;
#pragma unroll
        for (int kk = 0; kk < 16; kk += 8) {
            uint32_t a[4][4], b[4][2];
#pragma unroll
            for (int mt = 0; mt < 4; mt++) {
                const uint32_t* pr = au + (wm + (mt << 4) + g) * R3_STRIDE + so + kk;
                a[mt][0] = pr[t];
                a[mt][1] = pr[8 * R3_STRIDE + t];
                a[mt][2] = pr[t + 4];
                a[mt][3] = pr[8 * R3_STRIDE + t + 4];
            }
#pragma unroll
            for (int nt = 0; nt < 4; nt++) {
                const uint32_t* pr = vu + (size_t)(so + kk + t) * VS_STRIDE +
                                     wn + (nt << 3) + g;
                b[nt][0] = pr[0];
                b[nt][1] = pr[4 * VS_STRIDE];
            }
#pragma unroll
            for (int mt = 0; mt < 4; mt++)
#pragma unroll
                for (int nt = 0; nt < 4; nt++)
                    mma_tf32(acc[mt][nt], a[mt], b[nt]);
        }
        __syncthreads();
    }

    const float* rs = rowsum + (size_t)z * NPQ;
#pragma unroll
    for (int mt = 0; mt < 4; mt++) {
        int m = m0 + wm + (mt << 4) + g;
        float i0 = 1.0f / rs[m];
        float i1 = 1.0f / rs[m + 8];
#pragma unroll
        for (int nt = 0; nt < 4; nt++) {
            int n = wn + (nt << 3) + 2 * t;
            float2 o0, o1;
            o0.x = acc[mt][nt][0] * i0; o0.y = acc[mt][nt][1] * i0;
            o1.x = acc[mt][nt][2] * i1; o1.y = acc[mt][nt][3] * i1;
            *reinterpret_cast<float2*>(C + (size_t)m * CDIM + n) = o0;
            *reinterpret_cast<float2*>(C + (size_t)(m + 8) * CDIM + n) = o1;
        }
    }
}

// ---------------------------------------------------------------------------
#define PROJ_SMEM (2 * 128 * R3_STRIDE * 4)          // 53248 B
#define SC_SMEM   (2 * 128 * SC_STRIDE * 4)          // 69632 B
#define OUT_SMEM  ((256 * R3_STRIDE + 48 * VS_STRIDE) * 4)  // 67072 B

extern "C" void kernel_launch(void* const* d_in, const int* in_sizes, int n_in,
                              void* d_out, int out_size)
{
    const float* Q  = (const float*)d_in[0];
    const float* K  = (const float*)d_in[1];
    const float* Wq = (const float*)d_in[2];
    const float* bq = (const float*)d_in[3];
    const float* Wk = (const float*)d_in[4];
    const float* bk = (const float*)d_in[5];
    const float* Wv = (const float*)d_in[6];
    const float* bv = (const float*)d_in[7];

    float* O    = (float*)d_out;
    float* Aavg = O + (size_t)BB * NPQ * CDIM;

    static float *pq = nullptr, *pk = nullptr, *pv = nullptr, *pP = nullptr,
                 *pR = nullptr;
    if (!pq) {
        cudaGetSymbolAddress((void**)&pq, g_q);
        cudaGetSymbolAddress((void**)&pk, g_k);
        cudaGetSymbolAddress((void**)&pv, g_v);
        cudaGetSymbolAddress((void**)&pP, g_P);
        cudaGetSymbolAddress((void**)&pR, g_rowsum);
        cudaFuncSetAttribute(proj_gemm,
                             cudaFuncAttributeMaxDynamicSharedMemorySize, PROJ_SMEM);
        cudaFuncSetAttribute(scores_gemm,
                             cudaFuncAttributeMaxDynamicSharedMemorySize, SC_SMEM);
        cudaFuncSetAttribute(out_gemm,
                             cudaFuncAttributeMaxDynamicSharedMemorySize, OUT_SMEM);
    }

    // zero row sums (graph-capturable async memset)
    cudaMemsetAsync(pR, 0, (size_t)BB * HH * NPQ * sizeof(float));

    // 1) projections (M=4096, N=K=1024), outputs tf32-rounded
    dim3 gp(CDIM / 128, (BB * NPQ) / 128);
    proj_gemm<<<gp, 256, PROJ_SMEM>>>(Q, Wq, bq, pq);
    proj_gemm<<<gp, 256, PROJ_SMEM>>>(K, Wk, bk, pk);
    proj_gemm<<<gp, 256, PROJ_SMEM>>>(K, Wv, bv, pv);

    // 2) P = round(exp(q.k/32)), rowsum accumulated
    dim3 gs(NRK / 128, NPQ / 128, BB * HH);
    scores_gemm<<<gs, 256, SC_SMEM>>>(pq, pk, pP, pR);

    // 3) A_avg = mean_{16}(P * inv)
    avg_kernel<<<BB * NPQ, 256>>>(pP, pR, Aavg);

    // 4) O = (P @ V) * inv
    dim3 go(NPQ / 256, BB * HH);
    out_gemm<<<go, 256, OUT_SMEM>>>(pP, pv, pR, O);
}

// round 8
// speedup vs baseline: 1.3363x; 1.1466x over previous
#include <cuda_runtime.h>
#include <cuda_fp16.h>
#include <cstdint>

#define BB   4
#define NPQ  1024
#define NRK  1024
#define CDIM 1024
#define HH   16
#define DH   64

// Scratch (static device arrays: allocation-guard safe)
__device__ float  g_q[(size_t)BB * NPQ * CDIM];
__device__ float  g_k[(size_t)BB * NRK * CDIM];
__device__ float  g_v[(size_t)BB * NRK * CDIM];
__device__ __half g_P[(size_t)BB * HH * NPQ * NRK];   // 128 MB (fp16)
__device__ float  g_rowsum[(size_t)BB * HH * NPQ];    // 256 KB

// ---------------------------------------------------------------------------
// helpers
// ---------------------------------------------------------------------------
__device__ __forceinline__ uint32_t f2tf32(float x) {
    uint32_t y;
    asm("cvt.rna.tf32.f32 %0, %1;" : "=r"(y) : "f"(x));
    return y;
}
__device__ __forceinline__ float rnd_tf32(float x) {
    return __uint_as_float(f2tf32(x));
}

__device__ __forceinline__ void mma_tf32(float c[4], const uint32_t a[4],
                                         const uint32_t b[2]) {
    asm volatile(
        "mma.sync.aligned.m16n8k8.row.col.f32.tf32.tf32.f32 "
        "{%0,%1,%2,%3}, {%4,%5,%6,%7}, {%8,%9}, {%0,%1,%2,%3};"
        : "+f"(c[0]), "+f"(c[1]), "+f"(c[2]), "+f"(c[3])
        : "r"(a[0]), "r"(a[1]), "r"(a[2]), "r"(a[3]), "r"(b[0]), "r"(b[1]));
}

__device__ __forceinline__ uint32_t smem_u32(const void* p) {
    uint32_t a;
    asm("{ .reg .u64 t; cvta.to.shared.u64 t, %1; cvt.u32.u64 %0, t; }"
        : "=r"(a) : "l"(p));
    return a;
}

#define CP_ASYNC16(dst, src) \
    asm volatile("cp.async.cg.shared.global [%0], [%1], 16;" \
                 :: "r"(dst), "l"(src) : "memory")
#define CP_COMMIT() asm volatile("cp.async.commit_group;" ::: "memory")
#define CP_WAIT1()  asm volatile("cp.async.wait_group 1;" ::: "memory")
#define CP_WAIT0()  asm volatile("cp.async.wait_group 0;" ::: "memory")

#define AS_STRIDE 36          // fp32, 2x16 + 4 pad
#define AS_WORDS  (256 * AS_STRIDE)
#define BS_STRIDE 36
#define SC_STRIDE 68          // scores single-shot K=64 + 4 pad
#define VS_STRIDE 72          // out-gemm V (fp32 k-major)
#define PH_STRIDE 40          // out-gemm A tile in halves: 2x16 + 8 pad

// ---------------------------------------------------------------------------
// Projection GEMM (NT): C = round_tf32(A*B^T + bias)   [R5 shape]
// Block 256x128, 8 warps (4m x 2n), warp 64x64, k-stage 16, 2-stage cp.async.
// ---------------------------------------------------------------------------
__global__ void __launch_bounds__(256, 1) proj_gemm(
    const float* __restrict__ Ag, const float* __restrict__ Bg,
    const float* __restrict__ bias, float* __restrict__ Cg)
{
    extern __shared__ float sm[];
    float* As = sm;                  // [256][36]
    float* Bs = sm + AS_WORDS;       // [128][36]

    const int tid = threadIdx.x;
    const int m0 = blockIdx.y << 8, n0 = blockIdx.x << 7;
    const int warp = tid >> 5, lane = tid & 31;
    const int g = lane >> 2, t = lane & 3;
    const int wm = (warp >> 1) << 6;
    const int wn = (warp & 1) << 6;

    const uint32_t sA = smem_u32(As);
    const uint32_t sB = smem_u32(Bs);
    const int lrow = tid >> 2;
    const int lc   = (tid & 3) << 2;

    auto load_stage = [&](int kt) {
        const int so = (kt & 1) << 4;
        const int k0 = kt << 4;
#pragma unroll
        for (int i = 0; i < 4; i++) {
            int r = lrow + (i << 6);
            CP_ASYNC16(sA + ((r * AS_STRIDE + so + lc) << 2),
                       Ag + (size_t)(m0 + r) * CDIM + k0 + lc);
        }
#pragma unroll
        for (int i = 0; i < 2; i++) {
            int r = lrow + (i << 6);
            CP_ASYNC16(sB + ((r * BS_STRIDE + so + lc) << 2),
                       Bg + (size_t)(n0 + r) * CDIM + k0 + lc);
        }
        CP_COMMIT();
    };

    float acc[4][8][4];
#pragma unroll
    for (int i = 0; i < 4; i++)
#pragma unroll
        for (int j = 0; j < 8; j++)
#pragma unroll
            for (int l = 0; l < 4; l++) acc[i][j][l] = 0.f;

    const int KT = CDIM / 16;
    load_stage(0);

    for (int kt = 0; kt < KT; kt++) {
        const bool pf = (kt + 1 < KT);
        if (pf) { load_stage(kt + 1); CP_WAIT1(); } else { CP_WAIT0(); }
        __syncthreads();

        const int so = (kt & 1) << 4;
#pragma unroll
        for (int kk = 0; kk < 16; kk += 8) {
            uint32_t a[4][4], b[8][2];
#pragma unroll
            for (int mt = 0; mt < 4; mt++) {
                const float* pr = As + (wm + (mt << 4) + g) * AS_STRIDE + so + kk;
                a[mt][0] = f2tf32(pr[t]);
                a[mt][1] = f2tf32(pr[8 * AS_STRIDE + t]);
                a[mt][2] = f2tf32(pr[t + 4]);
                a[mt][3] = f2tf32(pr[8 * AS_STRIDE + t + 4]);
            }
#pragma unroll
            for (int nt = 0; nt < 8; nt++) {
                const float* pr = Bs + (wn + (nt << 3) + g) * BS_STRIDE + so + kk;
                b[nt][0] = f2tf32(pr[t]);
                b[nt][1] = f2tf32(pr[t + 4]);
            }
#pragma unroll
            for (int mt = 0; mt < 4; mt++)
#pragma unroll
                for (int nt = 0; nt < 8; nt++)
                    mma_tf32(acc[mt][nt], a[mt], b[nt]);
        }
        __syncthreads();
    }

#pragma unroll
    for (int mt = 0; mt < 4; mt++) {
        int m = m0 + wm + (mt << 4) + g;
#pragma unroll
        for (int nt = 0; nt < 8; nt++) {
            int n = n0 + wn + (nt << 3) + 2 * t;
            float b0v = bias[n], b1v = bias[n + 1];
            float2 o0, o1;
            o0.x = rnd_tf32(acc[mt][nt][0] + b0v);
            o0.y = rnd_tf32(acc[mt][nt][1] + b1v);
            o1.x = rnd_tf32(acc[mt][nt][2] + b0v);
            o1.y = rnd_tf32(acc[mt][nt][3] + b1v);
            *reinterpret_cast<float2*>(Cg + (size_t)m * CDIM + n) = o0;
            *reinterpret_cast<float2*>(Cg + (size_t)(m + 8) * CDIM + n) = o1;
        }
    }
}

// ---------------------------------------------------------------------------
// Scores: P = fp16(exp(q.k^T/32)), rowsum += sums of the fp16-rounded values.
// Inputs pre-rounded tf32 (raw-bit fragments). Tile 128x128, K=64 one shot.
// ---------------------------------------------------------------------------
__global__ void __launch_bounds__(256, 2) scores_gemm(
    const float* __restrict__ qg, const float* __restrict__ kg,
    __half* __restrict__ P, float* __restrict__ rowsum)
{
    extern __shared__ float sm[];
    float* qs = sm;                      // [128][68]
    float* ks = sm + 128 * SC_STRIDE;    // [128][68]

    const int tid = threadIdx.x;
    const int z = blockIdx.z;
    const long long zb = z >> 4, zh = z & 15;
    const float* A = qg + zb * ((long long)NPQ * CDIM) + zh * DH;
    const float* B = kg + zb * ((long long)NRK * CDIM) + zh * DH;
    __half* C = P + (long long)z * NPQ * NRK;
    const int m0 = blockIdx.y << 7, n0 = blockIdx.x << 7;

    const int warp = tid >> 5, lane = tid & 31;
    const int g = lane >> 2, t = lane & 3;
    const int wm = (warp >> 1) << 5;
    const int wn = (warp & 1) << 6;

    const uint32_t sq = smem_u32(qs);
    const uint32_t sk = smem_u32(ks);
    const int lrow = tid >> 1;
    const int lh = (tid & 1) << 5;

    {
        const float* pa = A + (size_t)(m0 + lrow) * CDIM + lh;
        const float* pb = B + (size_t)(n0 + lrow) * CDIM + lh;
        const uint32_t dq = sq + ((lrow * SC_STRIDE + lh) << 2);
        const uint32_t dk = sk + ((lrow * SC_STRIDE + lh) << 2);
#pragma unroll
        for (int i = 0; i < 8; i++) {
            CP_ASYNC16(dq + (i << 4), pa + (i << 2));
            CP_ASYNC16(dk + (i << 4), pb + (i << 2));
        }
        CP_COMMIT();
    }
    CP_WAIT0();
    __syncthreads();

    float acc[2][8][4];
#pragma unroll
    for (int i = 0; i < 2; i++)
#pragma unroll
        for (int j = 0; j < 8; j++)
#pragma unroll
            for (int l = 0; l < 4; l++) acc[i][j][l] = 0.f;

    const uint32_t* qu = reinterpret_cast<const uint32_t*>(qs);
    const uint32_t* ku = reinterpret_cast<const uint32_t*>(ks);
#pragma unroll
    for (int kk = 0; kk < 64; kk += 8) {
        uint32_t a[2][4], b[8][2];
#pragma unroll
        for (int mt = 0; mt < 2; mt++) {
            const uint32_t* pr = qu + (wm + (mt << 4) + g) * SC_STRIDE + kk;
            a[mt][0] = pr[t];
            a[mt][1] = pr[8 * SC_STRIDE + t];
            a[mt][2] = pr[t + 4];
            a[mt][3] = pr[8 * SC_STRIDE + t + 4];
        }
#pragma unroll
        for (int nt = 0; nt < 8; nt++) {
            const uint32_t* pr = ku + (wn + (nt << 3) + g) * SC_STRIDE + kk;
            b[nt][0] = pr[t];
            b[nt][1] = pr[t + 4];
        }
#pragma unroll
        for (int mt = 0; mt < 2; mt++)
#pragma unroll
            for (int nt = 0; nt < 8; nt++)
                mma_tf32(acc[mt][nt], a[mt], b[nt]);
    }

    const float alpha = 0.03125f;
#pragma unroll
    for (int mt = 0; mt < 2; mt++) {
        int m = m0 + wm + (mt << 4) + g;
        float r0 = 0.f, r1 = 0.f;
#pragma unroll
        for (int nt = 0; nt < 8; nt++) {
            int n = n0 + wn + (nt << 3) + 2 * t;
            __half h0 = __float2half_rn(__expf(acc[mt][nt][0] * alpha));
            __half h1 = __float2half_rn(__expf(acc[mt][nt][1] * alpha));
            __half h2 = __float2half_rn(__expf(acc[mt][nt][2] * alpha));
            __half h3 = __float2half_rn(__expf(acc[mt][nt][3] * alpha));
            r0 += __half2float(h0) + __half2float(h1);
            r1 += __half2float(h2) + __half2float(h3);
            *reinterpret_cast<__half2*>(C + (size_t)m * NRK + n) =
                __halves2half2(h0, h1);
            *reinterpret_cast<__half2*>(C + (size_t)(m + 8) * NRK + n) =
                __halves2half2(h2, h3);
        }
        r0 += __shfl_xor_sync(0xffffffffu, r0, 1);
        r0 += __shfl_xor_sync(0xffffffffu, r0, 2);
        r1 += __shfl_xor_sync(0xffffffffu, r1, 1);
        r1 += __shfl_xor_sync(0xffffffffu, r1, 2);
        if (t == 0) {
            float* rs = rowsum + (size_t)z * NPQ;
            atomicAdd(&rs[m], r0);
            atomicAdd(&rs[m + 8], r1);
        }
    }
}

// ---------------------------------------------------------------------------
// A_avg[b',q,r] = (1/16) sum_{b,j} P[b,4b'+j,q,r] * inv[b,4b'+j,q]
// ---------------------------------------------------------------------------
__global__ void __launch_bounds__(256) avg_kernel(
    const __half* __restrict__ P, const float* __restrict__ rowsum,
    float* __restrict__ Aavg)
{
    __shared__ float sinv[16];
    const int q = blockIdx.x & 1023;
    const int bp = blockIdx.x >> 10;
    const int t = threadIdx.x;

    if (t < 16) {
        int b = t >> 2, j = t & 3;
        sinv[t] = 1.0f / rowsum[((size_t)(b * HH + bp * 4 + j)) * NPQ + q];
    }
    __syncthreads();

    float ax = 0.f, ay = 0.f, az = 0.f, aw = 0.f;
#pragma unroll
    for (int b = 0; b < 4; b++)
#pragma unroll
        for (int j = 0; j < 4; j++) {
            const __half* p = P + ((((size_t)(b * HH + bp * 4 + j)) << 10 | q) << 10);
            __half2 h01 = *reinterpret_cast<const __half2*>(p + t * 4);
            __half2 h23 = *reinterpret_cast<const __half2*>(p + t * 4 + 2);
            float2 f01 = __half22float2(h01);
            float2 f23 = __half22float2(h23);
            float f = sinv[b * 4 + j];
            ax = fmaf(f01.x, f, ax); ay = fmaf(f01.y, f, ay);
            az = fmaf(f23.x, f, az); aw = fmaf(f23.y, f, aw);
        }
    const float sc = 1.0f / 16.0f;
    float4 o = make_float4(ax * sc, ay * sc, az * sc, aw * sc);
    *reinterpret_cast<float4*>(Aavg + (((size_t)blockIdx.x) << 10) + t * 4) = o;
}

// ---------------------------------------------------------------------------
// Out GEMM (NN): O[q, h*64+d] = inv[q]*sum_r P[q,r]*V[r, h*64+d]   [R5 shape]
// Block 256x64, 8 warps (4m x 2n), warp 64x32, 2-stage cp.async.
// P is fp16 in smem -> cvt f16->f32 (exact tf32). V pre-rounded fp32 (raw).
// ---------------------------------------------------------------------------
__global__ void __launch_bounds__(256, 1) out_gemm(
    const __half* __restrict__ Pg, const float* __restrict__ Vg,
    const float* __restrict__ rowsum, float* __restrict__ Og)
{
    extern __shared__ float sm[];
    __half* Ah = reinterpret_cast<__half*>(sm);      // [256][40] halves
    float* Vs = sm + (256 * PH_STRIDE) / 2;          // [32][72] fp32

    const int tid = threadIdx.x;
    const int z = blockIdx.y;
    const long long zb = z >> 4, zh = z & 15;
    const __half* A = Pg + ((long long)z * NPQ) * NRK;
    const float* B = Vg + zb * ((long long)NRK * CDIM) + zh * DH;
    float* C = Og + zb * ((long long)NPQ * CDIM) + zh * DH;

    const int m0 = blockIdx.x << 8;
    const int warp = tid >> 5, lane = tid & 31;
    const int g = lane >> 2, t = lane & 3;
    const int wm = (warp >> 1) << 6;
    const int wn = (warp & 1) << 5;

    const uint32_t sA = smem_u32(Ah);
    const uint32_t sV = smem_u32(Vs);

    const int vk = tid >> 4;
    const int vc = (tid & 15) << 2;

    auto load_stage = [&](int kt) {
        const int so = (kt & 1) << 4;      // halves
        const int k0 = kt << 4;
        // A: 256 rows x 16 halves; thread = one row, two 16B chunks
        CP_ASYNC16(sA + ((tid * PH_STRIDE + so) << 1),
                   A + (size_t)(m0 + tid) * NRK + k0);
        CP_ASYNC16(sA + ((tid * PH_STRIDE + so + 8) << 1),
                   A + (size_t)(m0 + tid) * NRK + k0 + 8);
        // V: 16 rows x 64 floats
        CP_ASYNC16(sV + (((so + vk) * VS_STRIDE + vc) << 2),
                   B + (size_t)(k0 + vk) * CDIM + vc);
        CP_COMMIT();
    };

    float acc[4][4][4];
#pragma unroll
    for (int i = 0; i < 4; i++)
#pragma unroll
        for (int j = 0; j < 4; j++)
#pragma unroll
            for (int l = 0; l < 4; l++) acc[i][j][l] = 0.f;

    const int KT = NRK / 16;
    load_stage(0);

    const uint32_t* vu = reinterpret_cast<const uint32_t*>(Vs);

    for (int kt = 0; kt < KT; kt++) {
        const bool pf = (kt + 1 < KT);
        if (pf) { load_stage(kt + 1); CP_WAIT1(); } else { CP_WAIT0(); }
        __syncthreads();

        const int so = (kt & 1) << 4;
#pragma unroll
        for (int kk = 0; kk < 16; kk += 8) {
            uint32_t a[4][4], b[4][2];
#pragma unroll
            for (int mt = 0; mt < 4; mt++) {
                const __half* pr = Ah + (wm + (mt << 4) + g) * PH_STRIDE + so + kk;
                a[mt][0] = __float_as_uint(__half2float(pr[t]));
                a[mt][1] = __float_as_uint(__half2float(pr[8 * PH_STRIDE + t]));
                a[mt][2] = __float_as_uint(__half2float(pr[t + 4]));
                a[mt][3] = __float_as_uint(__half2float(pr[8 * PH_STRIDE + t + 4]));
            }
#pragma unroll
            for (int nt = 0; nt < 4; nt++) {
                const uint32_t* pr = vu + (size_t)(so + kk + t) * VS_STRIDE +
                                     wn + (nt << 3) + g;
                b[nt][0] = pr[0];
                b[nt][1] = pr[4 * VS_STRIDE];
            }
#pragma unroll
            for (int mt = 0; mt < 4; mt++)
#pragma unroll
                for (int nt = 0; nt < 4; nt++)
                    mma_tf32(acc[mt][nt], a[mt], b[nt]);
        }
        __syncthreads();
    }

    const float* rs = rowsum + (size_t)z * NPQ;
#pragma unroll
    for (int mt = 0; mt < 4; mt++) {
        int m = m0 + wm + (mt << 4) + g;
        float i0 = 1.0f / rs[m];
        float i1 = 1.0f / rs[m + 8];
#pragma unroll
        for (int nt = 0; nt < 4; nt++) {
            int n = wn + (nt << 3) + 2 * t;
            float2 o0, o1;
            o0.x = acc[mt][nt][0] * i0; o0.y = acc[mt][nt][1] * i0;
            o1.x = acc[mt][nt][2] * i1; o1.y = acc[mt][nt][3] * i1;
            *reinterpret_cast<float2*>(C + (size_t)m * CDIM + n) = o0;
            *reinterpret_cast<float2*>(C + (size_t)(m + 8) * CDIM + n) = o1;
        }
    }
}

// ---------------------------------------------------------------------------
#define PROJ_SMEM ((AS_WORDS + 128 * BS_STRIDE) * 4)                 // 55296 B
#define SC_SMEM   (2 * 128 * SC_STRIDE * 4)                          // 69632 B
#define OUT_SMEM  (256 * PH_STRIDE * 2 + 32 * VS_STRIDE * 4)         // 29696 B

extern "C" void kernel_launch(void* const* d_in, const int* in_sizes, int n_in,
                              void* d_out, int out_size)
{
    const float* Q  = (const float*)d_in[0];
    const float* K  = (const float*)d_in[1];
    const float* Wq = (const float*)d_in[2];
    const float* bq = (const float*)d_in[3];
    const float* Wk = (const float*)d_in[4];
    const float* bk = (const float*)d_in[5];
    const float* Wv = (const float*)d_in[6];
    const float* bv = (const float*)d_in[7];

    float* O    = (float*)d_out;
    float* Aavg = O + (size_t)BB * NPQ * CDIM;

    static float *pq = nullptr, *pk = nullptr, *pv = nullptr, *pR = nullptr;
    static __half* pP = nullptr;
    if (!pq) {
        cudaGetSymbolAddress((void**)&pq, g_q);
        cudaGetSymbolAddress((void**)&pk, g_k);
        cudaGetSymbolAddress((void**)&pv, g_v);
        cudaGetSymbolAddress((void**)&pP, g_P);
        cudaGetSymbolAddress((void**)&pR, g_rowsum);
        cudaFuncSetAttribute(proj_gemm,
                             cudaFuncAttributeMaxDynamicSharedMemorySize, PROJ_SMEM);
        cudaFuncSetAttribute(scores_gemm,
                             cudaFuncAttributeMaxDynamicSharedMemorySize, SC_SMEM);
        cudaFuncSetAttribute(out_gemm,
                             cudaFuncAttributeMaxDynamicSharedMemorySize, OUT_SMEM);
    }

    // zero row sums (graph-capturable async memset)
    cudaMemsetAsync(pR, 0, (size_t)BB * HH * NPQ * sizeof(float));

    // 1) projections (M=4096, N=K=1024), outputs tf32-rounded
    dim3 gp(CDIM / 128, (BB * NPQ) / 256);
    proj_gemm<<<gp, 256, PROJ_SMEM>>>(Q, Wq, bq, pq);
    proj_gemm<<<gp, 256, PROJ_SMEM>>>(K, Wk, bk, pk);
    proj_gemm<<<gp, 256, PROJ_SMEM>>>(K, Wv, bv, pv);

    // 2) P = fp16(exp(q.k/32)), rowsum over rounded values
    dim3 gs(NRK / 128, NPQ / 128, BB * HH);
    scores_gemm<<<gs, 256, SC_SMEM>>>(pq, pk, pP, pR);

    // 3) A_avg = mean_{16}(P * inv)
    avg_kernel<<<BB * NPQ, 256>>>(pP, pR, Aavg);

    // 4) O = (P @ V) * inv
    dim3 go(NPQ / 256, BB * HH);
    out_gemm<<<go, 256, OUT_SMEM>>>(pP, pv, pR, O);
}

// round 9
// speedup vs baseline: 1.5499x; 1.1598x over previous
#include <cuda_runtime.h>
#include <cuda_fp16.h>
#include <cstdint>

#define BB   4
#define NPQ  1024
#define NRK  1024
#define CDIM 1024
#define HH   16
#define DH   64

// Scratch (static device arrays: allocation-guard safe)
__device__ __half g_q[(size_t)BB * NPQ * CDIM];       // 8 MB each
__device__ __half g_k[(size_t)BB * NRK * CDIM];
__device__ __half g_v[(size_t)BB * NRK * CDIM];
__device__ __half g_P[(size_t)BB * HH * NPQ * NRK];   // 128 MB
__device__ float  g_rowsum[(size_t)BB * HH * NPQ];    // 256 KB

// ---------------------------------------------------------------------------
// helpers
// ---------------------------------------------------------------------------
__device__ __forceinline__ uint32_t f2tf32(float x) {
    uint32_t y;
    asm("cvt.rna.tf32.f32 %0, %1;" : "=r"(y) : "f"(x));
    return y;
}

__device__ __forceinline__ void mma_tf32(float c[4], const uint32_t a[4],
                                         const uint32_t b[2]) {
    asm volatile(
        "mma.sync.aligned.m16n8k8.row.col.f32.tf32.tf32.f32 "
        "{%0,%1,%2,%3}, {%4,%5,%6,%7}, {%8,%9}, {%0,%1,%2,%3};"
        : "+f"(c[0]), "+f"(c[1]), "+f"(c[2]), "+f"(c[3])
        : "r"(a[0]), "r"(a[1]), "r"(a[2]), "r"(a[3]), "r"(b[0]), "r"(b[1]));
}

__device__ __forceinline__ void mma_f16(float c[4], const uint32_t a[4],
                                        const uint32_t b[2]) {
    asm volatile(
        "mma.sync.aligned.m16n8k16.row.col.f32.f16.f16.f32 "
        "{%0,%1,%2,%3}, {%4,%5,%6,%7}, {%8,%9}, {%0,%1,%2,%3};"
        : "+f"(c[0]), "+f"(c[1]), "+f"(c[2]), "+f"(c[3])
        : "r"(a[0]), "r"(a[1]), "r"(a[2]), "r"(a[3]), "r"(b[0]), "r"(b[1]));
}

#define LDSM_X4(r, addr) \
    asm volatile("ldmatrix.sync.aligned.m8n8.x4.shared.b16 {%0,%1,%2,%3}, [%4];" \
        : "=r"((r)[0]), "=r"((r)[1]), "=r"((r)[2]), "=r"((r)[3]) : "r"(addr))
#define LDSM_X2(r, addr) \
    asm volatile("ldmatrix.sync.aligned.m8n8.x2.shared.b16 {%0,%1}, [%2];" \
        : "=r"((r)[0]), "=r"((r)[1]) : "r"(addr))
#define LDSM_X2_T(r, addr) \
    asm volatile("ldmatrix.sync.aligned.m8n8.x2.trans.shared.b16 {%0,%1}, [%2];" \
        : "=r"((r)[0]), "=r"((r)[1]) : "r"(addr))

__device__ __forceinline__ uint32_t smem_u32(const void* p) {
    uint32_t a;
    asm("{ .reg .u64 t; cvta.to.shared.u64 t, %1; cvt.u32.u64 %0, t; }"
        : "=r"(a) : "l"(p));
    return a;
}

#define CP_ASYNC16(dst, src) \
    asm volatile("cp.async.cg.shared.global [%0], [%1], 16;" \
                 :: "r"(dst), "l"(src) : "memory")
#define CP_COMMIT() asm volatile("cp.async.commit_group;" ::: "memory")
#define CP_WAIT1()  asm volatile("cp.async.wait_group 1;" ::: "memory")
#define CP_WAIT0()  asm volatile("cp.async.wait_group 0;" ::: "memory")

#define AS_STRIDE 36   // proj fp32 A tile
#define BS_STRIDE 36   // proj fp32 B tile
#define SCH 72         // scores q/k halves stride: 144B -> 9r mod 8 distinct
#define PH  40         // out P halves stride: 80B -> 5r mod 8 distinct
#define VSH 72         // out V halves stride

// ---------------------------------------------------------------------------
// Projection GEMM (NT): C = fp16(A*B^T + bias)   [R5 shape, tf32 mma]
// Block 256x128, 8 warps (4m x 2n), warp 64x64, k-stage 16, 2-stage cp.async.
// ---------------------------------------------------------------------------
__global__ void __launch_bounds__(256, 1) proj_gemm(
    const float* __restrict__ Ag, const float* __restrict__ Bg,
    const float* __restrict__ bias, __half* __restrict__ Cg)
{
    extern __shared__ float sm[];
    float* As = sm;                       // [256][36]
    float* Bs = sm + 256 * AS_STRIDE;     // [128][36]

    const int tid = threadIdx.x;
    const int m0 = blockIdx.y << 8, n0 = blockIdx.x << 7;
    const int warp = tid >> 5, lane = tid & 31;
    const int g = lane >> 2, t = lane & 3;
    const int wm = (warp >> 1) << 6;
    const int wn = (warp & 1) << 6;

    const uint32_t sA = smem_u32(As);
    const uint32_t sB = smem_u32(Bs);
    const int lrow = tid >> 2;
    const int lc   = (tid & 3) << 2;

    auto load_stage = [&](int kt) {
        const int so = (kt & 1) << 4;
        const int k0 = kt << 4;
#pragma unroll
        for (int i = 0; i < 4; i++) {
            int r = lrow + (i << 6);
            CP_ASYNC16(sA + ((r * AS_STRIDE + so + lc) << 2),
                       Ag + (size_t)(m0 + r) * CDIM + k0 + lc);
        }
#pragma unroll
        for (int i = 0; i < 2; i++) {
            int r = lrow + (i << 6);
            CP_ASYNC16(sB + ((r * BS_STRIDE + so + lc) << 2),
                       Bg + (size_t)(n0 + r) * CDIM + k0 + lc);
        }
        CP_COMMIT();
    };

    float acc[4][8][4];
#pragma unroll
    for (int i = 0; i < 4; i++)
#pragma unroll
        for (int j = 0; j < 8; j++)
#pragma unroll
            for (int l = 0; l < 4; l++) acc[i][j][l] = 0.f;

    const int KT = CDIM / 16;
    load_stage(0);

    for (int kt = 0; kt < KT; kt++) {
        const bool pf = (kt + 1 < KT);
        if (pf) { load_stage(kt + 1); CP_WAIT1(); } else { CP_WAIT0(); }
        __syncthreads();

        const int so = (kt & 1) << 4;
#pragma unroll
        for (int kk = 0; kk < 16; kk += 8) {
            uint32_t a[4][4], b[8][2];
#pragma unroll
            for (int mt = 0; mt < 4; mt++) {
                const float* pr = As + (wm + (mt << 4) + g) * AS_STRIDE + so + kk;
                a[mt][0] = f2tf32(pr[t]);
                a[mt][1] = f2tf32(pr[8 * AS_STRIDE + t]);
                a[mt][2] = f2tf32(pr[t + 4]);
                a[mt][3] = f2tf32(pr[8 * AS_STRIDE + t + 4]);
            }
#pragma unroll
            for (int nt = 0; nt < 8; nt++) {
                const float* pr = Bs + (wn + (nt << 3) + g) * BS_STRIDE + so + kk;
                b[nt][0] = f2tf32(pr[t]);
                b[nt][1] = f2tf32(pr[t + 4]);
            }
#pragma unroll
            for (int mt = 0; mt < 4; mt++)
#pragma unroll
                for (int nt = 0; nt < 8; nt++)
                    mma_tf32(acc[mt][nt], a[mt], b[nt]);
        }
        __syncthreads();
    }

#pragma unroll
    for (int mt = 0; mt < 4; mt++) {
        int m = m0 + wm + (mt << 4) + g;
#pragma unroll
        for (int nt = 0; nt < 8; nt++) {
            int n = n0 + wn + (nt << 3) + 2 * t;
            float b0v = bias[n], b1v = bias[n + 1];
            *reinterpret_cast<__half2*>(Cg + (size_t)m * CDIM + n) =
                __floats2half2_rn(acc[mt][nt][0] + b0v, acc[mt][nt][1] + b1v);
            *reinterpret_cast<__half2*>(Cg + (size_t)(m + 8) * CDIM + n) =
                __floats2half2_rn(acc[mt][nt][2] + b0v, acc[mt][nt][3] + b1v);
        }
    }
}

// ---------------------------------------------------------------------------
// Scores: P = fp16(exp(q.k^T/32)), rowsum += rounded sums.
// q,k fp16, m16n8k16 HMMA + ldmatrix. Tile 128x128, K=64 one shot.
// ---------------------------------------------------------------------------
__global__ void __launch_bounds__(256, 2) scores_gemm(
    const __half* __restrict__ qg, const __half* __restrict__ kg,
    __half* __restrict__ P, float* __restrict__ rowsum)
{
    extern __shared__ __half sh[];
    __half* qs = sh;                // [128][72]
    __half* ks = sh + 128 * SCH;    // [128][72]

    const int tid = threadIdx.x;
    const int z = blockIdx.z;
    const long long zb = z >> 4, zh = z & 15;
    const __half* A = qg + zb * ((long long)NPQ * CDIM) + zh * DH;
    const __half* B = kg + zb * ((long long)NRK * CDIM) + zh * DH;
    __half* C = P + (long long)z * NPQ * NRK;
    const int m0 = blockIdx.y << 7, n0 = blockIdx.x << 7;

    const int warp = tid >> 5, lane = tid & 31;
    const int g = lane >> 2, t = lane & 3;
    const int wm = (warp >> 1) << 5;   // 0,32,64,96
    const int wn = (warp & 1) << 6;    // 0,64

    const uint32_t sq = smem_u32(qs);
    const uint32_t sk = smem_u32(ks);
    const int lrow = tid >> 1;
    const int lh = (tid & 1) << 5;     // 0/32 halves

    {
        const __half* pa = A + (size_t)(m0 + lrow) * CDIM + lh;
        const __half* pb = B + (size_t)(n0 + lrow) * CDIM + lh;
        const uint32_t dq = sq + ((lrow * SCH + lh) << 1);
        const uint32_t dk = sk + ((lrow * SCH + lh) << 1);
#pragma unroll
        for (int i = 0; i < 4; i++) {
            CP_ASYNC16(dq + (i << 4), pa + (i << 3));
            CP_ASYNC16(dk + (i << 4), pb + (i << 3));
        }
        CP_COMMIT();
    }
    CP_WAIT0();
    __syncthreads();

    float acc[2][8][4];
#pragma unroll
    for (int i = 0; i < 2; i++)
#pragma unroll
        for (int j = 0; j < 8; j++)
#pragma unroll
            for (int l = 0; l < 4; l++) acc[i][j][l] = 0.f;

    const int arow = lane & 15, acol = (lane >> 4) << 3;
    const int brow = lane & 7,  bcol = ((lane >> 3) & 1) << 3;

#pragma unroll
    for (int kk = 0; kk < 64; kk += 16) {
        uint32_t a[2][4], b[8][2];
#pragma unroll
        for (int mt = 0; mt < 2; mt++)
            LDSM_X4(a[mt], sq + (((wm + (mt << 4) + arow) * SCH) + kk + acol) * 2);
#pragma unroll
        for (int nt = 0; nt < 8; nt++)
            LDSM_X2(b[nt], sk + (((wn + (nt << 3) + brow) * SCH) + kk + bcol) * 2);
#pragma unroll
        for (int mt = 0; mt < 2; mt++)
#pragma unroll
            for (int nt = 0; nt < 8; nt++)
                mma_f16(acc[mt][nt], a[mt], b[nt]);
    }

    const float alpha = 0.03125f;
#pragma unroll
    for (int mt = 0; mt < 2; mt++) {
        int m = m0 + wm + (mt << 4) + g;
        float r0 = 0.f, r1 = 0.f;
#pragma unroll
        for (int nt = 0; nt < 8; nt++) {
            int n = n0 + wn + (nt << 3) + 2 * t;
            __half h0 = __float2half_rn(__expf(acc[mt][nt][0] * alpha));
            __half h1 = __float2half_rn(__expf(acc[mt][nt][1] * alpha));
            __half h2 = __float2half_rn(__expf(acc[mt][nt][2] * alpha));
            __half h3 = __float2half_rn(__expf(acc[mt][nt][3] * alpha));
            r0 += __half2float(h0) + __half2float(h1);
            r1 += __half2float(h2) + __half2float(h3);
            *reinterpret_cast<__half2*>(C + (size_t)m * NRK + n) =
                __halves2half2(h0, h1);
            *reinterpret_cast<__half2*>(C + (size_t)(m + 8) * NRK + n) =
                __halves2half2(h2, h3);
        }
        r0 += __shfl_xor_sync(0xffffffffu, r0, 1);
        r0 += __shfl_xor_sync(0xffffffffu, r0, 2);
        r1 += __shfl_xor_sync(0xffffffffu, r1, 1);
        r1 += __shfl_xor_sync(0xffffffffu, r1, 2);
        if (t == 0) {
            float* rs = rowsum + (size_t)z * NPQ;
            atomicAdd(&rs[m], r0);
            atomicAdd(&rs[m + 8], r1);
        }
    }
}

// ---------------------------------------------------------------------------
// A_avg[b',q,r] = (1/16) sum_{b,j} P[b,4b'+j,q,r] * inv[b,4b'+j,q]
// ---------------------------------------------------------------------------
__global__ void __launch_bounds__(256) avg_kernel(
    const __half* __restrict__ P, const float* __restrict__ rowsum,
    float* __restrict__ Aavg)
{
    __shared__ float sinv[16];
    const int q = blockIdx.x & 1023;
    const int bp = blockIdx.x >> 10;
    const int t = threadIdx.x;

    if (t < 16) {
        int b = t >> 2, j = t & 3;
        sinv[t] = 1.0f / rowsum[((size_t)(b * HH + bp * 4 + j)) * NPQ + q];
    }
    __syncthreads();

    float ax = 0.f, ay = 0.f, az = 0.f, aw = 0.f;
#pragma unroll
    for (int b = 0; b < 4; b++)
#pragma unroll
        for (int j = 0; j < 4; j++) {
            const __half* p = P + ((((size_t)(b * HH + bp * 4 + j)) << 10 | q) << 10);
            __half2 h01 = *reinterpret_cast<const __half2*>(p + t * 4);
            __half2 h23 = *reinterpret_cast<const __half2*>(p + t * 4 + 2);
            float2 f01 = __half22float2(h01);
            float2 f23 = __half22float2(h23);
            float f = sinv[b * 4 + j];
            ax = fmaf(f01.x, f, ax); ay = fmaf(f01.y, f, ay);
            az = fmaf(f23.x, f, az); aw = fmaf(f23.y, f, aw);
        }
    const float sc = 1.0f / 16.0f;
    float4 o = make_float4(ax * sc, ay * sc, az * sc, aw * sc);
    *reinterpret_cast<float4*>(Aavg + (((size_t)blockIdx.x) << 10) + t * 4) = o;
}

// ---------------------------------------------------------------------------
// Out GEMM (NN): O = inv * (P @ V), fp16 HMMA + ldmatrix(.trans for V).
// Block 256x64, 8 warps (4m x 2n), warp 64x32, k-stage 16, 2-stage cp.async.
// ---------------------------------------------------------------------------
__global__ void __launch_bounds__(256, 1) out_gemm(
    const __half* __restrict__ Pg, const __half* __restrict__ Vg,
    const float* __restrict__ rowsum, float* __restrict__ Og)
{
    extern __shared__ __half sh[];
    __half* Ah = sh;                  // [256][40]
    __half* Vs = sh + 256 * PH;       // [32][72]

    const int tid = threadIdx.x;
    const int z = blockIdx.y;
    const long long zb = z >> 4, zh = z & 15;
    const __half* A = Pg + ((long long)z * NPQ) * NRK;
    const __half* B = Vg + zb * ((long long)NRK * CDIM) + zh * DH;
    float* C = Og + zb * ((long long)NPQ * CDIM) + zh * DH;

    const int m0 = blockIdx.x << 8;
    const int warp = tid >> 5, lane = tid & 31;
    const int g = lane >> 2, t = lane & 3;
    const int wm = (warp >> 1) << 6;   // 0..192
    const int wn = (warp & 1) << 5;    // 0,32

    const uint32_t sA = smem_u32(Ah);
    const uint32_t sV = smem_u32(Vs);

    auto load_stage = [&](int kt) {
        const int so = (kt & 1) << 4;      // halves / k-rows
        const int k0 = kt << 4;
        CP_ASYNC16(sA + ((tid * PH + so) << 1),
                   A + (size_t)(m0 + tid) * NRK + k0);
        CP_ASYNC16(sA + ((tid * PH + so + 8) << 1),
                   A + (size_t)(m0 + tid) * NRK + k0 + 8);
        if (tid < 128) {
            int row = tid >> 3, col = (tid & 7) << 3;
            CP_ASYNC16(sV + (((so + row) * VSH + col) << 1),
                       B + (size_t)(k0 + row) * CDIM + col);
        }
        CP_COMMIT();
    };

    float acc[4][4][4];
#pragma unroll
    for (int i = 0; i < 4; i++)
#pragma unroll
        for (int j = 0; j < 4; j++)
#pragma unroll
            for (int l = 0; l < 4; l++) acc[i][j][l] = 0.f;

    const int KT = NRK / 16;
    load_stage(0);

    const int arow = lane & 15, acol = (lane >> 4) << 3;
    const int bkrow = lane & 15;

    for (int kt = 0; kt < KT; kt++) {
        const bool pf = (kt + 1 < KT);
        if (pf) { load_stage(kt + 1); CP_WAIT1(); } else { CP_WAIT0(); }
        __syncthreads();

        const int so = (kt & 1) << 4;
        uint32_t a[4][4], b[4][2];
#pragma unroll
        for (int mt = 0; mt < 4; mt++)
            LDSM_X4(a[mt], sA + (((wm + (mt << 4) + arow) * PH) + so + acol) * 2);
#pragma unroll
        for (int nt = 0; nt < 4; nt++)
            LDSM_X2_T(b[nt], sV + (((so + bkrow) * VSH) + wn + (nt << 3)) * 2);
#pragma unroll
        for (int mt = 0; mt < 4; mt++)
#pragma unroll
            for (int nt = 0; nt < 4; nt++)
                mma_f16(acc[mt][nt], a[mt], b[nt]);
        __syncthreads();
    }

    const float* rs = rowsum + (size_t)z * NPQ;
#pragma unroll
    for (int mt = 0; mt < 4; mt++) {
        int m = m0 + wm + (mt << 4) + g;
        float i0 = 1.0f / rs[m];
        float i1 = 1.0f / rs[m + 8];
#pragma unroll
        for (int nt = 0; nt < 4; nt++) {
            int n = wn + (nt << 3) + 2 * t;
            float2 o0, o1;
            o0.x = acc[mt][nt][0] * i0; o0.y = acc[mt][nt][1] * i0;
            o1.x = acc[mt][nt][2] * i1; o1.y = acc[mt][nt][3] * i1;
            *reinterpret_cast<float2*>(C + (size_t)m * CDIM + n) = o0;
            *reinterpret_cast<float2*>(C + (size_t)(m + 8) * CDIM + n) = o1;
        }
    }
}

// ---------------------------------------------------------------------------
#define PROJ_SMEM ((256 * AS_STRIDE + 128 * BS_STRIDE) * 4)   // 55296 B
#define SC_SMEM   (2 * 128 * SCH * 2)                         // 36864 B
#define OUT_SMEM  ((256 * PH + 32 * VSH) * 2)                 // 25088 B

extern "C" void kernel_launch(void* const* d_in, const int* in_sizes, int n_in,
                              void* d_out, int out_size)
{
    const float* Q  = (const float*)d_in[0];
    const float* K  = (const float*)d_in[1];
    const float* Wq = (const float*)d_in[2];
    const float* bq = (const float*)d_in[3];
    const float* Wk = (const float*)d_in[4];
    const float* bk = (const float*)d_in[5];
    const float* Wv = (const float*)d_in[6];
    const float* bv = (const float*)d_in[7];

    float* O    = (float*)d_out;
    float* Aavg = O + (size_t)BB * NPQ * CDIM;

    static __half *pq = nullptr, *pk = nullptr, *pv = nullptr, *pP = nullptr;
    static float* pR = nullptr;
    if (!pq) {
        cudaGetSymbolAddress((void**)&pq, g_q);
        cudaGetSymbolAddress((void**)&pk, g_k);
        cudaGetSymbolAddress((void**)&pv, g_v);
        cudaGetSymbolAddress((void**)&pP, g_P);
        cudaGetSymbolAddress((void**)&pR, g_rowsum);
        cudaFuncSetAttribute(proj_gemm,
                             cudaFuncAttributeMaxDynamicSharedMemorySize, PROJ_SMEM);
        cudaFuncSetAttribute(scores_gemm,
                             cudaFuncAttributeMaxDynamicSharedMemorySize, SC_SMEM);
        cudaFuncSetAttribute(out_gemm,
                             cudaFuncAttributeMaxDynamicSharedMemorySize, OUT_SMEM);
    }

    // zero row sums (graph-capturable async memset)
    cudaMemsetAsync(pR, 0, (size_t)BB * HH * NPQ * sizeof(float));

    // 1) projections (M=4096, N=K=1024), outputs fp16
    dim3 gp(CDIM / 128, (BB * NPQ) / 256);
    proj_gemm<<<gp, 256, PROJ_SMEM>>>(Q, Wq, bq, pq);
    proj_gemm<<<gp, 256, PROJ_SMEM>>>(K, Wk, bk, pk);
    proj_gemm<<<gp, 256, PROJ_SMEM>>>(K, Wv, bv, pv);

    // 2) P = fp16(exp(q.k/32)), rowsum over rounded values
    dim3 gs(NRK / 128, NPQ / 128, BB * HH);
    scores_gemm<<<gs, 256, SC_SMEM>>>(pq, pk, pP, pR);

    // 3) A_avg = mean_{16}(P * inv)
    avg_kernel<<<BB * NPQ, 256>>>(pP, pR, Aavg);

    // 4) O = (P @ V) * inv
    dim3 go(NPQ / 256, BB * HH);
    out_gemm<<<go, 256, OUT_SMEM>>>(pP, pv, pR, O);
}

// round 10
// speedup vs baseline: 1.8452x; 1.1906x over previous
#include <cuda_runtime.h>
#include <cuda_fp16.h>
#include <cstdint>

#define BB   4
#define NPQ  1024
#define NRK  1024
#define CDIM 1024
#define HH   16
#define DH   64

// Scratch (static device arrays: allocation-guard safe)
__device__ __half g_Qh[(size_t)BB * NPQ * CDIM];      // raw inputs, fp16
__device__ __half g_Kh[(size_t)BB * NRK * CDIM];
__device__ __half g_Wh[3 * (size_t)CDIM * CDIM];      // Wq, Wk, Wv fp16
__device__ __half g_q[(size_t)BB * NPQ * CDIM];       // projected q/k/v
__device__ __half g_k[(size_t)BB * NRK * CDIM];
__device__ __half g_v[(size_t)BB * NRK * CDIM];
__device__ __half g_P[(size_t)BB * HH * NPQ * NRK];   // 128 MB
__device__ float  g_rowsum[(size_t)BB * HH * NPQ];    // 256 KB

// ---------------------------------------------------------------------------
// helpers
// ---------------------------------------------------------------------------
__device__ __forceinline__ void mma_f16(float c[4], const uint32_t a[4],
                                        const uint32_t b[2]) {
    asm volatile(
        "mma.sync.aligned.m16n8k16.row.col.f32.f16.f16.f32 "
        "{%0,%1,%2,%3}, {%4,%5,%6,%7}, {%8,%9}, {%0,%1,%2,%3};"
        : "+f"(c[0]), "+f"(c[1]), "+f"(c[2]), "+f"(c[3])
        : "r"(a[0]), "r"(a[1]), "r"(a[2]), "r"(a[3]), "r"(b[0]), "r"(b[1]));
}

#define LDSM_X4(r, addr) \
    asm volatile("ldmatrix.sync.aligned.m8n8.x4.shared.b16 {%0,%1,%2,%3}, [%4];" \
        : "=r"((r)[0]), "=r"((r)[1]), "=r"((r)[2]), "=r"((r)[3]) : "r"(addr))
#define LDSM_X2(r, addr) \
    asm volatile("ldmatrix.sync.aligned.m8n8.x2.shared.b16 {%0,%1}, [%2];" \
        : "=r"((r)[0]), "=r"((r)[1]) : "r"(addr))
#define LDSM_X2_T(r, addr) \
    asm volatile("ldmatrix.sync.aligned.m8n8.x2.trans.shared.b16 {%0,%1}, [%2];" \
        : "=r"((r)[0]), "=r"((r)[1]) : "r"(addr))

__device__ __forceinline__ uint32_t smem_u32(const void* p) {
    uint32_t a;
    asm("{ .reg .u64 t; cvta.to.shared.u64 t, %1; cvt.u32.u64 %0, t; }"
        : "=r"(a) : "l"(p));
    return a;
}

#define CP_ASYNC16(dst, src) \
    asm volatile("cp.async.cg.shared.global [%0], [%1], 16;" \
                 :: "r"(dst), "l"(src) : "memory")
#define CP_COMMIT() asm volatile("cp.async.commit_group;" ::: "memory")
#define CP_WAIT1()  asm volatile("cp.async.wait_group 1;" ::: "memory")
#define CP_WAIT0()  asm volatile("cp.async.wait_group 0;" ::: "memory")

#define SCH 72   // scores q/k halves stride: 9r mod 8 distinct
#define PH  40   // 16+16 k-halves + 8 pad: 20r mod 32 distinct over 8 rows
#define VSH 72   // out V halves stride

// ---------------------------------------------------------------------------
// fp32 -> fp16 conversion (grid-stride over float4 units)
// ---------------------------------------------------------------------------
__global__ void __launch_bounds__(256) f2h_kernel(
    const float* __restrict__ in, __half* __restrict__ out, int n4)
{
    int i = blockIdx.x * 256 + threadIdx.x;
    if (i >= n4) return;
    float4 v = reinterpret_cast<const float4*>(in)[i];
    __half2* o = reinterpret_cast<__half2*>(out) + 2 * (size_t)i;
    o[0] = __floats2half2_rn(v.x, v.y);
    o[1] = __floats2half2_rn(v.z, v.w);
}

// ---------------------------------------------------------------------------
// Projection GEMM (NT, fp16 HMMA): C = fp16(A*B^T + bias)
// Block 256x128, 8 warps (4m x 2n), warp 64x64, k-stage 16, 2-stage cp.async.
// ---------------------------------------------------------------------------
__global__ void __launch_bounds__(256, 1) proj_gemm(
    const __half* __restrict__ Ag, const __half* __restrict__ Bg,
    const float* __restrict__ bias, __half* __restrict__ Cg)
{
    extern __shared__ __half sh[];
    __half* Ah = sh;                 // [256][40]
    __half* Bh = sh + 256 * PH;      // [128][40]

    const int tid = threadIdx.x;
    const int m0 = blockIdx.y << 8, n0 = blockIdx.x << 7;
    const int warp = tid >> 5, lane = tid & 31;
    const int g = lane >> 2, t = lane & 3;
    const int wm = (warp >> 1) << 6;   // 0,64,128,192
    const int wn = (warp & 1) << 6;    // 0,64

    const uint32_t sA = smem_u32(Ah);
    const uint32_t sB = smem_u32(Bh);

    auto load_stage = [&](int kt) {
        const int so = (kt & 1) << 4;
        const int k0 = kt << 4;
        // A: 256 rows x 16 halves; thread = row, two 16B chunks
        CP_ASYNC16(sA + ((tid * PH + so) << 1),
                   Ag + (size_t)(m0 + tid) * CDIM + k0);
        CP_ASYNC16(sA + ((tid * PH + so + 8) << 1),
                   Ag + (size_t)(m0 + tid) * CDIM + k0 + 8);
        // B: 128 rows x 16 halves; thread -> (row = tid>>1, chunk = tid&1)
        {
            int r = tid >> 1, c = (tid & 1) << 3;
            CP_ASYNC16(sB + ((r * PH + so + c) << 1),
                       Bg + (size_t)(n0 + r) * CDIM + k0 + c);
        }
        CP_COMMIT();
    };

    float acc[4][8][4];
#pragma unroll
    for (int i = 0; i < 4; i++)
#pragma unroll
        for (int j = 0; j < 8; j++)
#pragma unroll
            for (int l = 0; l < 4; l++) acc[i][j][l] = 0.f;

    const int KT = CDIM / 16;
    load_stage(0);

    const int arow = lane & 15, acol = (lane >> 4) << 3;
    const int brow = lane & 7,  bcol = ((lane >> 3) & 1) << 3;

    for (int kt = 0; kt < KT; kt++) {
        const bool pf = (kt + 1 < KT);
        if (pf) { load_stage(kt + 1); CP_WAIT1(); } else { CP_WAIT0(); }
        __syncthreads();

        const int so = (kt & 1) << 4;
        uint32_t a[4][4], b[8][2];
#pragma unroll
        for (int mt = 0; mt < 4; mt++)
            LDSM_X4(a[mt], sA + (((wm + (mt << 4) + arow) * PH) + so + acol) * 2);
#pragma unroll
        for (int nt = 0; nt < 8; nt++)
            LDSM_X2(b[nt], sB + (((wn + (nt << 3) + brow) * PH) + so + bcol) * 2);
#pragma unroll
        for (int mt = 0; mt < 4; mt++)
#pragma unroll
            for (int nt = 0; nt < 8; nt++)
                mma_f16(acc[mt][nt], a[mt], b[nt]);
        __syncthreads();
    }

#pragma unroll
    for (int mt = 0; mt < 4; mt++) {
        int m = m0 + wm + (mt << 4) + g;
#pragma unroll
        for (int nt = 0; nt < 8; nt++) {
            int n = n0 + wn + (nt << 3) + 2 * t;
            float b0v = bias[n], b1v = bias[n + 1];
            *reinterpret_cast<__half2*>(Cg + (size_t)m * CDIM + n) =
                __floats2half2_rn(acc[mt][nt][0] + b0v, acc[mt][nt][1] + b1v);
            *reinterpret_cast<__half2*>(Cg + (size_t)(m + 8) * CDIM + n) =
                __floats2half2_rn(acc[mt][nt][2] + b0v, acc[mt][nt][3] + b1v);
        }
    }
}

// ---------------------------------------------------------------------------
// Scores: P = fp16(exp(q.k^T/32)), rowsum += rounded sums.  [R9, unchanged]
// ---------------------------------------------------------------------------
__global__ void __launch_bounds__(256, 2) scores_gemm(
    const __half* __restrict__ qg, const __half* __restrict__ kg,
    __half* __restrict__ P, float* __restrict__ rowsum)
{
    extern __shared__ __half sh[];
    __half* qs = sh;                // [128][72]
    __half* ks = sh + 128 * SCH;    // [128][72]

    const int tid = threadIdx.x;
    const int z = blockIdx.z;
    const long long zb = z >> 4, zh = z & 15;
    const __half* A = qg + zb * ((long long)NPQ * CDIM) + zh * DH;
    const __half* B = kg + zb * ((long long)NRK * CDIM) + zh * DH;
    __half* C = P + (long long)z * NPQ * NRK;
    const int m0 = blockIdx.y << 7, n0 = blockIdx.x << 7;

    const int warp = tid >> 5, lane = tid & 31;
    const int g = lane >> 2, t = lane & 3;
    const int wm = (warp >> 1) << 5;
    const int wn = (warp & 1) << 6;

    const uint32_t sq = smem_u32(qs);
    const uint32_t sk = smem_u32(ks);
    const int lrow = tid >> 1;
    const int lh = (tid & 1) << 5;

    {
        const __half* pa = A + (size_t)(m0 + lrow) * CDIM + lh;
        const __half* pb = B + (size_t)(n0 + lrow) * CDIM + lh;
        const uint32_t dq = sq + ((lrow * SCH + lh) << 1);
        const uint32_t dk = sk + ((lrow * SCH + lh) << 1);
#pragma unroll
        for (int i = 0; i < 4; i++) {
            CP_ASYNC16(dq + (i << 4), pa + (i << 3));
            CP_ASYNC16(dk + (i << 4), pb + (i << 3));
        }
        CP_COMMIT();
    }
    CP_WAIT0();
    __syncthreads();

    float acc[2][8][4];
#pragma unroll
    for (int i = 0; i < 2; i++)
#pragma unroll
        for (int j = 0; j < 8; j++)
#pragma unroll
            for (int l = 0; l < 4; l++) acc[i][j][l] = 0.f;

    const int arow = lane & 15, acol = (lane >> 4) << 3;
    const int brow = lane & 7,  bcol = ((lane >> 3) & 1) << 3;

#pragma unroll
    for (int kk = 0; kk < 64; kk += 16) {
        uint32_t a[2][4], b[8][2];
#pragma unroll
        for (int mt = 0; mt < 2; mt++)
            LDSM_X4(a[mt], sq + (((wm + (mt << 4) + arow) * SCH) + kk + acol) * 2);
#pragma unroll
        for (int nt = 0; nt < 8; nt++)
            LDSM_X2(b[nt], sk + (((wn + (nt << 3) + brow) * SCH) + kk + bcol) * 2);
#pragma unroll
        for (int mt = 0; mt < 2; mt++)
#pragma unroll
            for (int nt = 0; nt < 8; nt++)
                mma_f16(acc[mt][nt], a[mt], b[nt]);
    }

    const float alpha = 0.03125f;
#pragma unroll
    for (int mt = 0; mt < 2; mt++) {
        int m = m0 + wm + (mt << 4) + g;
        float r0 = 0.f, r1 = 0.f;
#pragma unroll
        for (int nt = 0; nt < 8; nt++) {
            int n = n0 + wn + (nt << 3) + 2 * t;
            __half h0 = __float2half_rn(__expf(acc[mt][nt][0] * alpha));
            __half h1 = __float2half_rn(__expf(acc[mt][nt][1] * alpha));
            __half h2 = __float2half_rn(__expf(acc[mt][nt][2] * alpha));
            __half h3 = __float2half_rn(__expf(acc[mt][nt][3] * alpha));
            r0 += __half2float(h0) + __half2float(h1);
            r1 += __half2float(h2) + __half2float(h3);
            *reinterpret_cast<__half2*>(C + (size_t)m * NRK + n) =
                __halves2half2(h0, h1);
            *reinterpret_cast<__half2*>(C + (size_t)(m + 8) * NRK + n) =
                __halves2half2(h2, h3);
        }
        r0 += __shfl_xor_sync(0xffffffffu, r0, 1);
        r0 += __shfl_xor_sync(0xffffffffu, r0, 2);
        r1 += __shfl_xor_sync(0xffffffffu, r1, 1);
        r1 += __shfl_xor_sync(0xffffffffu, r1, 2);
        if (t == 0) {
            float* rs = rowsum + (size_t)z * NPQ;
            atomicAdd(&rs[m], r0);
            atomicAdd(&rs[m + 8], r1);
        }
    }
}

// ---------------------------------------------------------------------------
// A_avg  [R9, unchanged]
// ---------------------------------------------------------------------------
__global__ void __launch_bounds__(256) avg_kernel(
    const __half* __restrict__ P, const float* __restrict__ rowsum,
    float* __restrict__ Aavg)
{
    __shared__ float sinv[16];
    const int q = blockIdx.x & 1023;
    const int bp = blockIdx.x >> 10;
    const int t = threadIdx.x;

    if (t < 16) {
        int b = t >> 2, j = t & 3;
        sinv[t] = 1.0f / rowsum[((size_t)(b * HH + bp * 4 + j)) * NPQ + q];
    }
    __syncthreads();

    float ax = 0.f, ay = 0.f, az = 0.f, aw = 0.f;
#pragma unroll
    for (int b = 0; b < 4; b++)
#pragma unroll
        for (int j = 0; j < 4; j++) {
            const __half* p = P + ((((size_t)(b * HH + bp * 4 + j)) << 10 | q) << 10);
            __half2 h01 = *reinterpret_cast<const __half2*>(p + t * 4);
            __half2 h23 = *reinterpret_cast<const __half2*>(p + t * 4 + 2);
            float2 f01 = __half22float2(h01);
            float2 f23 = __half22float2(h23);
            float f = sinv[b * 4 + j];
            ax = fmaf(f01.x, f, ax); ay = fmaf(f01.y, f, ay);
            az = fmaf(f23.x, f, az); aw = fmaf(f23.y, f, aw);
        }
    const float sc = 1.0f / 16.0f;
    float4 o = make_float4(ax * sc, ay * sc, az * sc, aw * sc);
    *reinterpret_cast<float4*>(Aavg + (((size_t)blockIdx.x) << 10) + t * 4) = o;
}

// ---------------------------------------------------------------------------
// Out GEMM (NN): O = inv * (P @ V)  [R9, unchanged]
// ---------------------------------------------------------------------------
__global__ void __launch_bounds__(256, 1) out_gemm(
    const __half* __restrict__ Pg, const __half* __restrict__ Vg,
    const float* __restrict__ rowsum, float* __restrict__ Og)
{
    extern __shared__ __half sh[];
    __half* Ah = sh;                  // [256][40]
    __half* Vs = sh + 256 * PH;       // [32][72]

    const int tid = threadIdx.x;
    const int z = blockIdx.y;
    const long long zb = z >> 4, zh = z & 15;
    const __half* A = Pg + ((long long)z * NPQ) * NRK;
    const __half* B = Vg + zb * ((long long)NRK * CDIM) + zh * DH;
    float* C = Og + zb * ((long long)NPQ * CDIM) + zh * DH;

    const int m0 = blockIdx.x << 8;
    const int warp = tid >> 5, lane = tid & 31;
    const int g = lane >> 2, t = lane & 3;
    const int wm = (warp >> 1) << 6;
    const int wn = (warp & 1) << 5;

    const uint32_t sA = smem_u32(Ah);
    const uint32_t sV = smem_u32(Vs);

    auto load_stage = [&](int kt) {
        const int so = (kt & 1) << 4;
        const int k0 = kt << 4;
        CP_ASYNC16(sA + ((tid * PH + so) << 1),
                   A + (size_t)(m0 + tid) * NRK + k0);
        CP_ASYNC16(sA + ((tid * PH + so + 8) << 1),
                   A + (size_t)(m0 + tid) * NRK + k0 + 8);
        if (tid < 128) {
            int row = tid >> 3, col = (tid & 7) << 3;
            CP_ASYNC16(sV + (((so + row) * VSH + col) << 1),
                       B + (size_t)(k0 + row) * CDIM + col);
        }
        CP_COMMIT();
    };

    float acc[4][4][4];
#pragma unroll
    for (int i = 0; i < 4; i++)
#pragma unroll
        for (int j = 0; j < 4; j++)
#pragma unroll
            for (int l = 0; l < 4; l++) acc[i][j][l] = 0.f;

    const int KT = NRK / 16;
    load_stage(0);

    const int arow = lane & 15, acol = (lane >> 4) << 3;
    const int bkrow = lane & 15;

    for (int kt = 0; kt < KT; kt++) {
        const bool pf = (kt + 1 < KT);
        if (pf) { load_stage(kt + 1); CP_WAIT1(); } else { CP_WAIT0(); }
        __syncthreads();

        const int so = (kt & 1) << 4;
        uint32_t a[4][4], b[4][2];
#pragma unroll
        for (int mt = 0; mt < 4; mt++)
            LDSM_X4(a[mt], sA + (((wm + (mt << 4) + arow) * PH) + so + acol) * 2);
#pragma unroll
        for (int nt = 0; nt < 4; nt++)
            LDSM_X2_T(b[nt], sV + (((so + bkrow) * VSH) + wn + (nt << 3)) * 2);
#pragma unroll
        for (int mt = 0; mt < 4; mt++)
#pragma unroll
            for (int nt = 0; nt < 4; nt++)
                mma_f16(acc[mt][nt], a[mt], b[nt]);
        __syncthreads();
    }

    const float* rs = rowsum + (size_t)z * NPQ;
#pragma unroll
    for (int mt = 0; mt < 4; mt++) {
        int m = m0 + wm + (mt << 4) + g;
        float i0 = 1.0f / rs[m];
        float i1 = 1.0f / rs[m + 8];
#pragma unroll
        for (int nt = 0; nt < 4; nt++) {
            int n = wn + (nt << 3) + 2 * t;
            float2 o0, o1;
            o0.x = acc[mt][nt][0] * i0; o0.y = acc[mt][nt][1] * i0;
            o1.x = acc[mt][nt][2] * i1; o1.y = acc[mt][nt][3] * i1;
            *reinterpret_cast<float2*>(C + (size_t)m * CDIM + n) = o0;
            *reinterpret_cast<float2*>(C + (size_t)(m + 8) * CDIM + n) = o1;
        }
    }
}

// ---------------------------------------------------------------------------
#define PROJ_SMEM ((256 * PH + 128 * PH) * 2)    // 30720 B
#define SC_SMEM   (2 * 128 * SCH * 2)            // 36864 B
#define OUT_SMEM  ((256 * PH + 32 * VSH) * 2)    // 25088 B

extern "C" void kernel_launch(void* const* d_in, const int* in_sizes, int n_in,
                              void* d_out, int out_size)
{
    const float* Q  = (const float*)d_in[0];
    const float* K  = (const float*)d_in[1];
    const float* Wq = (const float*)d_in[2];
    const float* bq = (const float*)d_in[3];
    const float* Wk = (const float*)d_in[4];
    const float* bk = (const float*)d_in[5];
    const float* Wv = (const float*)d_in[6];
    const float* bv = (const float*)d_in[7];

    float* O    = (float*)d_out;
    float* Aavg = O + (size_t)BB * NPQ * CDIM;

    static __half *pQh = nullptr, *pKh = nullptr, *pWh = nullptr;
    static __half *pq = nullptr, *pk = nullptr, *pv = nullptr, *pP = nullptr;
    static float* pR = nullptr;
    if (!pq) {
        cudaGetSymbolAddress((void**)&pQh, g_Qh);
        cudaGetSymbolAddress((void**)&pKh, g_Kh);
        cudaGetSymbolAddress((void**)&pWh, g_Wh);
        cudaGetSymbolAddress((void**)&pq, g_q);
        cudaGetSymbolAddress((void**)&pk, g_k);
        cudaGetSymbolAddress((void**)&pv, g_v);
        cudaGetSymbolAddress((void**)&pP, g_P);
        cudaGetSymbolAddress((void**)&pR, g_rowsum);
        cudaFuncSetAttribute(proj_gemm,
                             cudaFuncAttributeMaxDynamicSharedMemorySize, PROJ_SMEM);
        cudaFuncSetAttribute(scores_gemm,
                             cudaFuncAttributeMaxDynamicSharedMemorySize, SC_SMEM);
        cudaFuncSetAttribute(out_gemm,
                             cudaFuncAttributeMaxDynamicSharedMemorySize, OUT_SMEM);
    }

    cudaMemsetAsync(pR, 0, (size_t)BB * HH * NPQ * sizeof(float));

    // 0) fp32 -> fp16 conversions
    const int NX4 = (BB * NPQ * CDIM) / 4;   // 1048576
    const int NW4 = (CDIM * CDIM) / 4;       // 262144
    f2h_kernel<<<(NX4 + 255) / 256, 256>>>(Q, pQh, NX4);
    f2h_kernel<<<(NX4 + 255) / 256, 256>>>(K, pKh, NX4);
    f2h_kernel<<<(NW4 + 255) / 256, 256>>>(Wq, pWh, NW4);
    f2h_kernel<<<(NW4 + 255) / 256, 256>>>(Wk, pWh + (size_t)CDIM * CDIM, NW4);
    f2h_kernel<<<(NW4 + 255) / 256, 256>>>(Wv, pWh + 2 * (size_t)CDIM * CDIM, NW4);

    // 1) projections (M=4096, N=K=1024), fp16 HMMA
    dim3 gp(CDIM / 128, (BB * NPQ) / 256);
    proj_gemm<<<gp, 256, PROJ_SMEM>>>(pQh, pWh, bq, pq);
    proj_gemm<<<gp, 256, PROJ_SMEM>>>(pKh, pWh + (size_t)CDIM * CDIM, bk, pk);
    proj_gemm<<<gp, 256, PROJ_SMEM>>>(pKh, pWh + 2 * (size_t)CDIM * CDIM, bv, pv);

    // 2) P = fp16(exp(q.k/32)), rowsum over rounded values
    dim3 gs(NRK / 128, NPQ / 128, BB * HH);
    scores_gemm<<<gs, 256, SC_SMEM>>>(pq, pk, pP, pR);

    // 3) A_avg = mean_{16}(P * inv)
    avg_kernel<<<BB * NPQ, 256>>>(pP, pR, Aavg);

    // 4) O = (P @ V) * inv
    dim3 go(NPQ / 256, BB * HH);
    out_gemm<<<go, 256, OUT_SMEM>>>(pP, pv, pR, O);
}